// round 7
// baseline (speedup 1.0000x reference)
#include <cuda_runtime.h>
#include <cuda_bf16.h>
#include <stdint.h>

// ============================================================================
// Problem constants
// ============================================================================
#define BA 8192
#define BB 16384
#define DIM 1024
#define LOSS_SCALE 20.0f

#define TM 128            // CTA rows
#define TN 128            // CTA cols per chunk
#define TKS 64            // K per pipeline stage
#define STAGES 4
#define NSPLIT 2          // column splits per row-block
#define CHUNKS (BB / NSPLIT / TN)     // 64 chunks of 128 cols per CTA
#define KSTAGES (DIM / TKS)           // 16 k-stages per chunk
#define TOTAL_STAGES (CHUNKS * KSTAGES)
#define ROWBLOCKS (BA / TM)           // 64
#define THREADS 512

// ============================================================================
// Device scratch
// ============================================================================
__device__ __nv_bfloat16 g_a_bf[(size_t)BA * DIM];   // 16 MB
__device__ __nv_bfloat16 g_b_bf[(size_t)BB * DIM];   // 32 MB
__device__ float g_inva[BA];
__device__ float g_invb[BB];
__device__ float g_pos[BA];
__device__ float g_pm[BA * NSPLIT];
__device__ float g_ps[BA * NSPLIT];
__device__ float g_part[ROWBLOCKS];

// ============================================================================
// SMEM layout (dynamic)
//   pitch per row = 72 bf16 = 144 B (conflict-free for ldmatrix, 16B aligned)
// ============================================================================
#define PITCH_B 144
#define STAGE_BYTES (128 * PITCH_B)          // 18432 per operand per stage
#define SM_A(stg) ((stg) * STAGE_BYTES)
#define SM_B(stg) (STAGES * STAGE_BYTES + (stg) * STAGE_BYTES)
#define SM_RED (2 * STAGES * STAGE_BYTES)               // float red[4][128][2]
#define SM_ROW (SM_RED + 4 * 128 * 2 * 4)               // float rowstate[128][2]
#define SMEM_TOTAL (SM_ROW + 128 * 2 * 4)               // 152576 (== verified R4 opt-in)

// ============================================================================
// PTX helpers
// ============================================================================
__device__ __forceinline__ uint32_t smem_to_u32(const void* p) {
    uint32_t a;
    asm("{ .reg .u64 t; cvta.to.shared.u64 t, %1; cvt.u32.u64 %0, t; }"
        : "=r"(a) : "l"(p));
    return a;
}

__device__ __forceinline__ void cp_async16(uint32_t s, const void* g) {
    asm volatile("cp.async.cg.shared.global [%0], [%1], 16;"
                 :: "r"(s), "l"(g) : "memory");
}
#define CP_COMMIT() asm volatile("cp.async.commit_group;" ::: "memory")
#define CP_WAIT(n)  asm volatile("cp.async.wait_group %0;" :: "n"(n) : "memory")

__device__ __forceinline__ void ldm_x4(uint32_t& r0, uint32_t& r1, uint32_t& r2,
                                       uint32_t& r3, uint32_t addr) {
    asm volatile("ldmatrix.sync.aligned.m8n8.x4.shared.b16 {%0,%1,%2,%3}, [%4];"
                 : "=r"(r0), "=r"(r1), "=r"(r2), "=r"(r3) : "r"(addr));
}

__device__ __forceinline__ void mma16816(float* c, uint32_t a0, uint32_t a1,
                                         uint32_t a2, uint32_t a3,
                                         uint32_t b0, uint32_t b1) {
    asm volatile(
        "mma.sync.aligned.m16n8k16.row.col.f32.bf16.bf16.f32 "
        "{%0,%1,%2,%3}, {%4,%5,%6,%7}, {%8,%9}, {%0,%1,%2,%3};"
        : "+f"(c[0]), "+f"(c[1]), "+f"(c[2]), "+f"(c[3])
        : "r"(a0), "r"(a1), "r"(a2), "r"(a3), "r"(b0), "r"(b1));
}

__device__ __forceinline__ void lse_merge(float& m, float& s, float om, float os) {
    float M = fmaxf(m, om);
    s = s * __expf(m - M) + os * __expf(om - M);
    m = M;
}

// ============================================================================
// Kernel 1: L2-normalize rows, write bf16 + inverse norms
// ============================================================================
__global__ void __launch_bounds__(128) normalize_kernel(const float* __restrict__ src, int which) {
    __nv_bfloat16* dst = which ? g_b_bf : g_a_bf;
    float* invn = which ? g_invb : g_inva;
    int row = blockIdx.x;
    int t = threadIdx.x;
    const float4* s4 = (const float4*)src + (size_t)row * (DIM / 4);
    float4 v0 = s4[t];
    float4 v1 = s4[t + 128];
    float ss = v0.x * v0.x + v0.y * v0.y + v0.z * v0.z + v0.w * v0.w
             + v1.x * v1.x + v1.y * v1.y + v1.z * v1.z + v1.w * v1.w;
    #pragma unroll
    for (int o = 16; o; o >>= 1) ss += __shfl_xor_sync(0xffffffffu, ss, o);
    __shared__ float ws[4];
    if ((t & 31) == 0) ws[t >> 5] = ss;
    __syncthreads();
    float inv = rsqrtf(ws[0] + ws[1] + ws[2] + ws[3]);
    if (t == 0) invn[row] = inv;
    __nv_bfloat162* d2 = (__nv_bfloat162*)dst + (size_t)row * (DIM / 2);
    d2[2 * t]           = __floats2bfloat162_rn(v0.x * inv, v0.y * inv);
    d2[2 * t + 1]       = __floats2bfloat162_rn(v0.z * inv, v0.w * inv);
    d2[256 + 2 * t]     = __floats2bfloat162_rn(v1.x * inv, v1.y * inv);
    d2[256 + 2 * t + 1] = __floats2bfloat162_rn(v1.z * inv, v1.w * inv);
}

// ============================================================================
// Kernel 2: positive logits (exact fp32)
// ============================================================================
__global__ void __launch_bounds__(128) pos_kernel(const float* __restrict__ a,
                                                  const float* __restrict__ b) {
    int row = blockIdx.x;
    int t = threadIdx.x;
    const float4* a4 = (const float4*)a + (size_t)row * (DIM / 4);
    const float4* b4 = (const float4*)b + (size_t)row * (DIM / 4);
    float4 x0 = a4[t], x1 = a4[t + 128];
    float4 y0 = b4[t], y1 = b4[t + 128];
    float acc = x0.x * y0.x + x0.y * y0.y + x0.z * y0.z + x0.w * y0.w
              + x1.x * y1.x + x1.y * y1.y + x1.z * y1.z + x1.w * y1.w;
    #pragma unroll
    for (int o = 16; o; o >>= 1) acc += __shfl_xor_sync(0xffffffffu, acc, o);
    __shared__ float ws[4];
    if ((t & 31) == 0) ws[t >> 5] = acc;
    __syncthreads();
    if (t == 0)
        g_pos[row] = LOSS_SCALE * (ws[0] + ws[1] + ws[2] + ws[3]) * g_inva[row] * g_invb[row];
}

// ============================================================================
// Kernel 3: fused GEMM (mma.sync bf16) + online row LSE
//   CTA: 128x128 tile, 512 threads, warp grid 4(m) x 4(n), warp tile 32x32.
// ============================================================================
__global__ void __launch_bounds__(THREADS, 1) gemm_lse_kernel() {
    extern __shared__ char sm[];
    uint32_t sb = smem_to_u32(sm);

    int t = threadIdx.x;
    int lane = t & 31;
    int w = t >> 5;
    int wm = w >> 2;             // 0..3
    int wn = w & 3;              // 0..3

    int rb = blockIdx.x / NSPLIT;
    int sp = blockIdx.x % NSPLIT;
    int col_base = sp * (BB / NSPLIT);

    float* red = (float*)(sm + SM_RED);          // [4][128][2]
    float* rowstate = (float*)(sm + SM_ROW);     // [128][2]
    if (t < 128) { rowstate[2 * t] = -1e30f; rowstate[2 * t + 1] = 0.f; }

    const char* a_gbase = (const char*)(g_a_bf + (size_t)(rb * TM) * DIM);
    const char* b_gbase = (const char*)(g_b_bf + (size_t)col_base * DIM);

    float acc[2][4][4];
    #pragma unroll
    for (int mt = 0; mt < 2; mt++)
        #pragma unroll
        for (int nt = 0; nt < 4; nt++)
            #pragma unroll
            for (int j = 0; j < 4; j++) acc[mt][nt][j] = 0.f;

    // --- issue one pipeline stage's cp.asyncs (1024 chunks of 16B / operand) ---
    auto issue = [&](int g) {
        if (g < TOTAL_STAGES) {
            int chunk = g >> 4;
            int kc = g & 15;
            int buf = g % STAGES;
            uint32_t sa = sb + SM_A(buf);
            uint32_t sbB = sb + SM_B(buf);
            size_t a_koff = (size_t)kc * (TKS * 2);
            size_t b_row0 = (size_t)chunk * TN;
            #pragma unroll
            for (int i = 0; i < 2; i++) {
                int c = t + i * THREADS;
                int row = c >> 3, seg = c & 7;
                cp_async16(sa + row * PITCH_B + seg * 16,
                           a_gbase + (size_t)row * (DIM * 2) + a_koff + seg * 16);
                cp_async16(sbB + row * PITCH_B + seg * 16,
                           b_gbase + (b_row0 + row) * (size_t)(DIM * 2) + a_koff + seg * 16);
            }
        }
        CP_COMMIT();
    };

    #pragma unroll
    for (int s = 0; s < STAGES - 1; s++) issue(s);

    for (int g = 0; g < TOTAL_STAGES; g++) {
        CP_WAIT(STAGES - 2);
        __syncthreads();
        issue(g + STAGES - 1);

        int buf = g % STAGES;
        // A: x4 ldmatrix, 16 rows per mt. lanes 0-15: rows, lanes 16-31: +16B k-half
        uint32_t saA = sb + SM_A(buf)
                     + (uint32_t)(wm * 32 + (lane & 15)) * PITCH_B
                     + ((lane >> 4) * 16);
        // B: x4 ldmatrix covering an nt-pair (16 B-rows).
        // matrix idx = lane>>3: [n-half = (lane>>4)*8, k-half = ((lane>>3)&1)*16]
        uint32_t sbB = sb + SM_B(buf)
                     + (uint32_t)(wn * 32 + ((lane >> 4) & 1) * 8 + (lane & 7)) * PITCH_B
                     + (((lane >> 3) & 1) * 16);

        #pragma unroll
        for (int kk = 0; kk < 4; kk++) {
            uint32_t a0[2], a1[2], a2[2], a3[2];
            uint32_t b0[4], b1[4];
            #pragma unroll
            for (int mt = 0; mt < 2; mt++)
                ldm_x4(a0[mt], a1[mt], a2[mt], a3[mt],
                       saA + mt * 16 * PITCH_B + kk * 32);
            #pragma unroll
            for (int p = 0; p < 2; p++)
                ldm_x4(b0[2 * p], b1[2 * p], b0[2 * p + 1], b1[2 * p + 1],
                       sbB + p * 16 * PITCH_B + kk * 32);
            #pragma unroll
            for (int mt = 0; mt < 2; mt++)
                #pragma unroll
                for (int nt = 0; nt < 4; nt++)
                    mma16816(acc[mt][nt], a0[mt], a1[mt], a2[mt], a3[mt],
                             b0[nt], b1[nt]);
        }

        if ((g & 15) == 15) {
            // ---- flash-LSE epilogue for this 128-col chunk ----
            #pragma unroll
            for (int mt = 0; mt < 2; mt++) {
                #pragma unroll
                for (int h = 0; h < 2; h++) {
                    float m = -1e30f;
                    #pragma unroll
                    for (int nt = 0; nt < 4; nt++) {
                        m = fmaxf(m, acc[mt][nt][2 * h]);
                        m = fmaxf(m, acc[mt][nt][2 * h + 1]);
                    }
                    m *= LOSS_SCALE;
                    float s = 0.f;
                    #pragma unroll
                    for (int nt = 0; nt < 4; nt++) {
                        s += __expf(LOSS_SCALE * acc[mt][nt][2 * h] - m);
                        s += __expf(LOSS_SCALE * acc[mt][nt][2 * h + 1] - m);
                    }
                    // quad reduce (lanes xor 1,2 share the same output row)
                    #pragma unroll
                    for (int off = 1; off <= 2; off <<= 1) {
                        float om = __shfl_xor_sync(0xffffffffu, m, off);
                        float os = __shfl_xor_sync(0xffffffffu, s, off);
                        lse_merge(m, s, om, os);
                    }
                    if ((lane & 3) == 0) {
                        int row = wm * 32 + mt * 16 + h * 8 + (lane >> 2);
                        red[(wn * 128 + row) * 2] = m;
                        red[(wn * 128 + row) * 2 + 1] = s;
                    }
                    #pragma unroll
                    for (int nt = 0; nt < 4; nt++) {
                        acc[mt][nt][2 * h] = 0.f;
                        acc[mt][nt][2 * h + 1] = 0.f;
                    }
                }
            }
            __syncthreads();
            if (t < 128) {
                float m = rowstate[2 * t], s = rowstate[2 * t + 1];
                #pragma unroll
                for (int cw = 0; cw < 4; cw++)
                    lse_merge(m, s, red[(cw * 128 + t) * 2], red[(cw * 128 + t) * 2 + 1]);
                rowstate[2 * t] = m;
                rowstate[2 * t + 1] = s;
            }
            // next loop iteration's __syncthreads orders red reuse
        }
    }

    __syncthreads();
    if (t < 128) {
        int row_g = rb * TM + t;
        g_pm[row_g * NSPLIT + sp] = rowstate[2 * t];
        g_ps[row_g * NSPLIT + sp] = rowstate[2 * t + 1];
    }
}

// ============================================================================
// Kernel 4/5: deterministic LSE combine + mean
// ============================================================================
__global__ void __launch_bounds__(128) combine_kernel() {
    int row = blockIdx.x * 128 + threadIdx.x;
    float M = -1e30f;
    float mv[NSPLIT], sv[NSPLIT];
    #pragma unroll
    for (int sp = 0; sp < NSPLIT; sp++) {
        mv[sp] = g_pm[row * NSPLIT + sp];
        sv[sp] = g_ps[row * NSPLIT + sp];
        M = fmaxf(M, mv[sp]);
    }
    float S = 0.f;
    #pragma unroll
    for (int sp = 0; sp < NSPLIT; sp++) S += sv[sp] * __expf(mv[sp] - M);
    float li = M + logf(S) - g_pos[row];
    #pragma unroll
    for (int o = 16; o; o >>= 1) li += __shfl_xor_sync(0xffffffffu, li, o);
    __shared__ float ws[4];
    if ((threadIdx.x & 31) == 0) ws[threadIdx.x >> 5] = li;
    __syncthreads();
    if (threadIdx.x == 0) g_part[blockIdx.x] = ws[0] + ws[1] + ws[2] + ws[3];
}

__global__ void __launch_bounds__(64) final_kernel(float* __restrict__ out) {
    float v = g_part[threadIdx.x];
    #pragma unroll
    for (int o = 16; o; o >>= 1) v += __shfl_xor_sync(0xffffffffu, v, o);
    __shared__ float ws[2];
    if ((threadIdx.x & 31) == 0) ws[threadIdx.x >> 5] = v;
    __syncthreads();
    if (threadIdx.x == 0) out[0] = (ws[0] + ws[1]) * (1.0f / (float)BA);
}

// ============================================================================
// Launch
// ============================================================================
extern "C" void kernel_launch(void* const* d_in, const int* in_sizes, int n_in,
                              void* d_out, int out_size) {
    (void)in_sizes; (void)n_in; (void)out_size;
    const float* a = (const float*)d_in[0];
    const float* b = (const float*)d_in[1];
    float* out = (float*)d_out;

    cudaFuncSetAttribute(gemm_lse_kernel,
                         cudaFuncAttributeMaxDynamicSharedMemorySize, SMEM_TOTAL);

    normalize_kernel<<<BA, 128>>>(a, 0);
    normalize_kernel<<<BB, 128>>>(b, 1);
    pos_kernel<<<BA, 128>>>(a, b);
    gemm_lse_kernel<<<ROWBLOCKS * NSPLIT, THREADS, SMEM_TOTAL>>>();
    combine_kernel<<<ROWBLOCKS, 128>>>();
    final_kernel<<<1, 64>>>(out);
}

// round 8
// speedup vs baseline: 1.2848x; 1.2848x over previous
#include <cuda_runtime.h>
#include <cuda_bf16.h>
#include <stdint.h>

// ============================================================================
// Problem constants
// ============================================================================
#define BA 8192
#define BB 16384
#define DIM 1024
#define LOSS_SCALE 20.0f

#define TM 128            // CTA rows
#define TN 256            // CTA cols per chunk
#define TKS 64            // K per pipeline stage
#define STAGES 2
#define NSPLIT 2          // column splits per row-block
#define CHUNKS (BB / NSPLIT / TN)     // 32 chunks of 256 cols per CTA
#define KSTAGES (DIM / TKS)           // 16 k-stages per chunk
#define TOTAL_STAGES (CHUNKS * KSTAGES)  // 512
#define ROWBLOCKS (BA / TM)           // 64
#define THREADS 256

// ============================================================================
// Device scratch
// ============================================================================
__device__ __nv_bfloat16 g_a_bf[(size_t)BA * DIM];   // 16 MB
__device__ __nv_bfloat16 g_b_bf[(size_t)BB * DIM];   // 32 MB
__device__ float g_inva[BA];
__device__ float g_invb[BB];
__device__ float g_pos[BA];
__device__ float g_pm[BA * NSPLIT];
__device__ float g_ps[BA * NSPLIT];
__device__ float g_part[ROWBLOCKS];

// ============================================================================
// SMEM layout (dynamic)
//   pitch per row = 72 bf16 = 144 B (conflict-free for ldmatrix, 16B aligned)
// ============================================================================
#define PITCH_B 144
#define A_STAGE_BYTES (128 * PITCH_B)        // 18432
#define B_STAGE_BYTES (256 * PITCH_B)        // 36864
#define SM_A(stg) ((stg) * A_STAGE_BYTES)
#define SM_B(stg) (STAGES * A_STAGE_BYTES + (stg) * B_STAGE_BYTES)
#define SM_RED (STAGES * (A_STAGE_BYTES + B_STAGE_BYTES))  // float red[4][128][2]
#define SM_ROW (SM_RED + 4 * 128 * 2 * 4)                  // float rowstate[128][2]
#define SMEM_TOTAL (SM_ROW + 128 * 2 * 4)                  // 115712 B

// ============================================================================
// PTX helpers
// ============================================================================
__device__ __forceinline__ uint32_t smem_to_u32(const void* p) {
    uint32_t a;
    asm("{ .reg .u64 t; cvta.to.shared.u64 t, %1; cvt.u32.u64 %0, t; }"
        : "=r"(a) : "l"(p));
    return a;
}

__device__ __forceinline__ void cp_async16(uint32_t s, const void* g) {
    asm volatile("cp.async.cg.shared.global [%0], [%1], 16;"
                 :: "r"(s), "l"(g) : "memory");
}
#define CP_COMMIT() asm volatile("cp.async.commit_group;" ::: "memory")
#define CP_WAIT(n)  asm volatile("cp.async.wait_group %0;" :: "n"(n) : "memory")

__device__ __forceinline__ void ldm_x4(uint32_t& r0, uint32_t& r1, uint32_t& r2,
                                       uint32_t& r3, uint32_t addr) {
    asm volatile("ldmatrix.sync.aligned.m8n8.x4.shared.b16 {%0,%1,%2,%3}, [%4];"
                 : "=r"(r0), "=r"(r1), "=r"(r2), "=r"(r3) : "r"(addr));
}

__device__ __forceinline__ void mma16816(float* c, uint32_t a0, uint32_t a1,
                                         uint32_t a2, uint32_t a3,
                                         uint32_t b0, uint32_t b1) {
    asm volatile(
        "mma.sync.aligned.m16n8k16.row.col.f32.bf16.bf16.f32 "
        "{%0,%1,%2,%3}, {%4,%5,%6,%7}, {%8,%9}, {%0,%1,%2,%3};"
        : "+f"(c[0]), "+f"(c[1]), "+f"(c[2]), "+f"(c[3])
        : "r"(a0), "r"(a1), "r"(a2), "r"(a3), "r"(b0), "r"(b1));
}

__device__ __forceinline__ void lse_merge(float& m, float& s, float om, float os) {
    float M = fmaxf(m, om);
    s = s * __expf(m - M) + os * __expf(om - M);
    m = M;
}

// ============================================================================
// Kernel 1: L2-normalize rows, write bf16 + inverse norms
// ============================================================================
__global__ void __launch_bounds__(128) normalize_kernel(const float* __restrict__ src, int which) {
    __nv_bfloat16* dst = which ? g_b_bf : g_a_bf;
    float* invn = which ? g_invb : g_inva;
    int row = blockIdx.x;
    int t = threadIdx.x;
    const float4* s4 = (const float4*)src + (size_t)row * (DIM / 4);
    float4 v0 = s4[t];
    float4 v1 = s4[t + 128];
    float ss = v0.x * v0.x + v0.y * v0.y + v0.z * v0.z + v0.w * v0.w
             + v1.x * v1.x + v1.y * v1.y + v1.z * v1.z + v1.w * v1.w;
    #pragma unroll
    for (int o = 16; o; o >>= 1) ss += __shfl_xor_sync(0xffffffffu, ss, o);
    __shared__ float ws[4];
    if ((t & 31) == 0) ws[t >> 5] = ss;
    __syncthreads();
    float inv = rsqrtf(ws[0] + ws[1] + ws[2] + ws[3]);
    if (t == 0) invn[row] = inv;
    __nv_bfloat162* d2 = (__nv_bfloat162*)dst + (size_t)row * (DIM / 2);
    d2[2 * t]           = __floats2bfloat162_rn(v0.x * inv, v0.y * inv);
    d2[2 * t + 1]       = __floats2bfloat162_rn(v0.z * inv, v0.w * inv);
    d2[256 + 2 * t]     = __floats2bfloat162_rn(v1.x * inv, v1.y * inv);
    d2[256 + 2 * t + 1] = __floats2bfloat162_rn(v1.z * inv, v1.w * inv);
}

// ============================================================================
// Kernel 2: positive logits (exact fp32)
// ============================================================================
__global__ void __launch_bounds__(128) pos_kernel(const float* __restrict__ a,
                                                  const float* __restrict__ b) {
    int row = blockIdx.x;
    int t = threadIdx.x;
    const float4* a4 = (const float4*)a + (size_t)row * (DIM / 4);
    const float4* b4 = (const float4*)b + (size_t)row * (DIM / 4);
    float4 x0 = a4[t], x1 = a4[t + 128];
    float4 y0 = b4[t], y1 = b4[t + 128];
    float acc = x0.x * y0.x + x0.y * y0.y + x0.z * y0.z + x0.w * y0.w
              + x1.x * y1.x + x1.y * y1.y + x1.z * y1.z + x1.w * y1.w;
    #pragma unroll
    for (int o = 16; o; o >>= 1) acc += __shfl_xor_sync(0xffffffffu, acc, o);
    __shared__ float ws[4];
    if ((t & 31) == 0) ws[t >> 5] = acc;
    __syncthreads();
    if (t == 0)
        g_pos[row] = LOSS_SCALE * (ws[0] + ws[1] + ws[2] + ws[3]) * g_inva[row] * g_invb[row];
}

// ============================================================================
// Kernel 3: fused GEMM (mma.sync bf16) + online row LSE
//   CTA: 128x256 tile, 256 threads, warp grid 2(m) x 4(n), warp tile 64x64.
// ============================================================================
__global__ void __launch_bounds__(THREADS, 1) gemm_lse_kernel() {
    extern __shared__ char sm[];
    uint32_t sb = smem_to_u32(sm);

    int t = threadIdx.x;
    int lane = t & 31;
    int w = t >> 5;
    int wm = w >> 2;             // 0..1
    int wn = w & 3;              // 0..3

    int rb = blockIdx.x / NSPLIT;
    int sp = blockIdx.x % NSPLIT;
    int col_base = sp * (BB / NSPLIT);

    float* red = (float*)(sm + SM_RED);          // [4][128][2]
    float* rowstate = (float*)(sm + SM_ROW);     // [128][2]
    if (t < 128) { rowstate[2 * t] = -1e30f; rowstate[2 * t + 1] = 0.f; }

    const char* a_gbase = (const char*)(g_a_bf + (size_t)(rb * TM) * DIM);
    const char* b_gbase = (const char*)(g_b_bf + (size_t)col_base * DIM);

    float acc[4][8][4];
    #pragma unroll
    for (int mt = 0; mt < 4; mt++)
        #pragma unroll
        for (int nt = 0; nt < 8; nt++)
            #pragma unroll
            for (int j = 0; j < 4; j++) acc[mt][nt][j] = 0.f;

    // --- issue one pipeline stage's cp.asyncs ---
    // A: 128 rows x 8 segs = 1024 x 16B; B: 256 rows x 8 segs = 2048 x 16B
    auto issue = [&](int g) {
        if (g < TOTAL_STAGES) {
            int chunk = g >> 4;
            int kc = g & 15;
            int buf = g % STAGES;
            uint32_t sa = sb + SM_A(buf);
            uint32_t sbB = sb + SM_B(buf);
            size_t a_koff = (size_t)kc * (TKS * 2);
            size_t b_row0 = (size_t)chunk * TN;
            #pragma unroll
            for (int i = 0; i < 4; i++) {
                int c = t + i * THREADS;
                int row = c >> 3, seg = c & 7;
                cp_async16(sa + row * PITCH_B + seg * 16,
                           a_gbase + (size_t)row * (DIM * 2) + a_koff + seg * 16);
            }
            #pragma unroll
            for (int i = 0; i < 8; i++) {
                int c = t + i * THREADS;
                int row = c >> 3, seg = c & 7;
                cp_async16(sbB + row * PITCH_B + seg * 16,
                           b_gbase + (b_row0 + row) * (size_t)(DIM * 2) + a_koff + seg * 16);
            }
        }
        CP_COMMIT();
    };

    #pragma unroll
    for (int s = 0; s < STAGES - 1; s++) issue(s);

    for (int g = 0; g < TOTAL_STAGES; g++) {
        CP_WAIT(STAGES - 2);
        __syncthreads();
        issue(g + STAGES - 1);

        int buf = g % STAGES;
        // A: x4 ldmatrix, 16 rows per mt. lanes 0-15: rows, lanes 16-31: +16B k-half
        uint32_t saA = sb + SM_A(buf)
                     + (uint32_t)(wm * 64 + (lane & 15)) * PITCH_B
                     + ((lane >> 4) * 16);
        // B: x4 ldmatrix covering an nt-pair (16 B-rows); mapping verified in R7:
        // lanes 0-15 -> n-halves of even/odd 8-col groups, lanes>>3&1 -> k-half
        uint32_t sbB = sb + SM_B(buf)
                     + (uint32_t)(wn * 64 + ((lane >> 4) & 1) * 8 + (lane & 7)) * PITCH_B
                     + (((lane >> 3) & 1) * 16);

        #pragma unroll
        for (int kk = 0; kk < 4; kk++) {
            uint32_t a0[4], a1[4], a2[4], a3[4];
            uint32_t b0[8], b1[8];
            #pragma unroll
            for (int mt = 0; mt < 4; mt++)
                ldm_x4(a0[mt], a1[mt], a2[mt], a3[mt],
                       saA + mt * 16 * PITCH_B + kk * 32);
            #pragma unroll
            for (int p = 0; p < 4; p++)
                ldm_x4(b0[2 * p], b1[2 * p], b0[2 * p + 1], b1[2 * p + 1],
                       sbB + p * 16 * PITCH_B + kk * 32);
            #pragma unroll
            for (int mt = 0; mt < 4; mt++)
                #pragma unroll
                for (int nt = 0; nt < 8; nt++)
                    mma16816(acc[mt][nt], a0[mt], a1[mt], a2[mt], a3[mt],
                             b0[nt], b1[nt]);
        }

        if ((g & 15) == 15) {
            // ---- flash-LSE epilogue for this 256-col chunk ----
            #pragma unroll
            for (int mt = 0; mt < 4; mt++) {
                #pragma unroll
                for (int h = 0; h < 2; h++) {
                    float m = -1e30f;
                    #pragma unroll
                    for (int nt = 0; nt < 8; nt++) {
                        m = fmaxf(m, acc[mt][nt][2 * h]);
                        m = fmaxf(m, acc[mt][nt][2 * h + 1]);
                    }
                    m *= LOSS_SCALE;
                    float s = 0.f;
                    #pragma unroll
                    for (int nt = 0; nt < 8; nt++) {
                        s += __expf(LOSS_SCALE * acc[mt][nt][2 * h] - m);
                        s += __expf(LOSS_SCALE * acc[mt][nt][2 * h + 1] - m);
                    }
                    // quad reduce (lanes xor 1,2 share the same output row)
                    #pragma unroll
                    for (int off = 1; off <= 2; off <<= 1) {
                        float om = __shfl_xor_sync(0xffffffffu, m, off);
                        float os = __shfl_xor_sync(0xffffffffu, s, off);
                        lse_merge(m, s, om, os);
                    }
                    if ((lane & 3) == 0) {
                        int row = wm * 64 + mt * 16 + h * 8 + (lane >> 2);
                        red[(wn * 128 + row) * 2] = m;
                        red[(wn * 128 + row) * 2 + 1] = s;
                    }
                    #pragma unroll
                    for (int nt = 0; nt < 8; nt++) {
                        acc[mt][nt][2 * h] = 0.f;
                        acc[mt][nt][2 * h + 1] = 0.f;
                    }
                }
            }
            __syncthreads();
            if (t < 128) {
                float m = rowstate[2 * t], s = rowstate[2 * t + 1];
                #pragma unroll
                for (int cw = 0; cw < 4; cw++)
                    lse_merge(m, s, red[(cw * 128 + t) * 2], red[(cw * 128 + t) * 2 + 1]);
                rowstate[2 * t] = m;
                rowstate[2 * t + 1] = s;
            }
            // next loop iteration's __syncthreads orders red reuse
        }
    }

    __syncthreads();
    if (t < 128) {
        int row_g = rb * TM + t;
        g_pm[row_g * NSPLIT + sp] = rowstate[2 * t];
        g_ps[row_g * NSPLIT + sp] = rowstate[2 * t + 1];
    }
}

// ============================================================================
// Kernel 4/5: deterministic LSE combine + mean
// ============================================================================
__global__ void __launch_bounds__(128) combine_kernel() {
    int row = blockIdx.x * 128 + threadIdx.x;
    float M = -1e30f;
    float mv[NSPLIT], sv[NSPLIT];
    #pragma unroll
    for (int sp = 0; sp < NSPLIT; sp++) {
        mv[sp] = g_pm[row * NSPLIT + sp];
        sv[sp] = g_ps[row * NSPLIT + sp];
        M = fmaxf(M, mv[sp]);
    }
    float S = 0.f;
    #pragma unroll
    for (int sp = 0; sp < NSPLIT; sp++) S += sv[sp] * __expf(mv[sp] - M);
    float li = M + logf(S) - g_pos[row];
    #pragma unroll
    for (int o = 16; o; o >>= 1) li += __shfl_xor_sync(0xffffffffu, li, o);
    __shared__ float ws[4];
    if ((threadIdx.x & 31) == 0) ws[threadIdx.x >> 5] = li;
    __syncthreads();
    if (threadIdx.x == 0) g_part[blockIdx.x] = ws[0] + ws[1] + ws[2] + ws[3];
}

__global__ void __launch_bounds__(64) final_kernel(float* __restrict__ out) {
    float v = g_part[threadIdx.x];
    #pragma unroll
    for (int o = 16; o; o >>= 1) v += __shfl_xor_sync(0xffffffffu, v, o);
    __shared__ float ws[2];
    if ((threadIdx.x & 31) == 0) ws[threadIdx.x >> 5] = v;
    __syncthreads();
    if (threadIdx.x == 0) out[0] = (ws[0] + ws[1]) * (1.0f / (float)BA);
}

// ============================================================================
// Launch
// ============================================================================
extern "C" void kernel_launch(void* const* d_in, const int* in_sizes, int n_in,
                              void* d_out, int out_size) {
    (void)in_sizes; (void)n_in; (void)out_size;
    const float* a = (const float*)d_in[0];
    const float* b = (const float*)d_in[1];
    float* out = (float*)d_out;

    cudaFuncSetAttribute(gemm_lse_kernel,
                         cudaFuncAttributeMaxDynamicSharedMemorySize, SMEM_TOTAL);

    normalize_kernel<<<BA, 128>>>(a, 0);
    normalize_kernel<<<BB, 128>>>(b, 1);
    pos_kernel<<<BA, 128>>>(a, b);
    gemm_lse_kernel<<<ROWBLOCKS * NSPLIT, THREADS, SMEM_TOTAL>>>();
    combine_kernel<<<ROWBLOCKS, 128>>>();
    final_kernel<<<1, 64>>>(out);
}

// round 9
// speedup vs baseline: 1.9630x; 1.5278x over previous
#include <cuda_runtime.h>
#include <cuda_bf16.h>
#include <stdint.h>

// ============================================================================
// Problem constants
// ============================================================================
#define BA 8192
#define BB 16384
#define DIM 1024
#define LOSS_SCALE 20.0f

#define TM 128            // CTA rows
#define TN 256            // CTA cols per chunk
#define TKS 64            // K elems (bytes) per pipeline stage
#define STAGES 3
#define NSPLIT 2          // column splits per row-block
#define CHUNKS (BB / NSPLIT / TN)     // 32 chunks of 256 cols per CTA
#define KSTAGES (DIM / TKS)           // 16 k-stages per chunk
#define TOTAL_STAGES (CHUNKS * KSTAGES)  // 512
#define ROWBLOCKS (BA / TM)           // 64
#define THREADS 256

// ============================================================================
// Device scratch
// ============================================================================
__device__ __align__(128) int8_t g_a_q[(size_t)BA * DIM];   // 8 MB
__device__ __align__(128) int8_t g_b_q[(size_t)BB * DIM];   // 16 MB
__device__ float g_sa20[BA];   // 20 * per-row dequant scale for A
__device__ float g_sb[BB];     // per-row dequant scale for B
__device__ float g_pos[BA];
__device__ float g_pm[BA * NSPLIT];
__device__ float g_ps[BA * NSPLIT];
__device__ float g_part[ROWBLOCKS];

// ============================================================================
// SMEM layout (dynamic). int8 rows: 64 data bytes + 16 pad = 80 B pitch.
// ldmatrix 8-row phases hit {0,80,32,112,64,16,96,48} mod 128 -> conflict-free.
// ============================================================================
#define PITCH_B 80
#define A_STAGE_BYTES (128 * PITCH_B)        // 10240
#define B_STAGE_BYTES (256 * PITCH_B)        // 20480
#define SM_A(stg) ((stg) * A_STAGE_BYTES)
#define SM_B(stg) (STAGES * A_STAGE_BYTES + (stg) * B_STAGE_BYTES)
#define SM_RED (STAGES * (A_STAGE_BYTES + B_STAGE_BYTES))  // float red[4][128][2]
#define SM_ROW (SM_RED + 4 * 128 * 2 * 4)                  // float rowstate[128][2]
#define SMEM_TOTAL (SM_ROW + 128 * 2 * 4)                  // 97280 B

// ============================================================================
// PTX helpers
// ============================================================================
__device__ __forceinline__ uint32_t smem_to_u32(const void* p) {
    uint32_t a;
    asm("{ .reg .u64 t; cvta.to.shared.u64 t, %1; cvt.u32.u64 %0, t; }"
        : "=r"(a) : "l"(p));
    return a;
}

__device__ __forceinline__ void cp_async16(uint32_t s, const void* g) {
    asm volatile("cp.async.cg.shared.global [%0], [%1], 16;"
                 :: "r"(s), "l"(g) : "memory");
}
#define CP_COMMIT() asm volatile("cp.async.commit_group;" ::: "memory")
#define CP_WAIT(n)  asm volatile("cp.async.wait_group %0;" :: "n"(n) : "memory")

__device__ __forceinline__ void ldm_x4(uint32_t& r0, uint32_t& r1, uint32_t& r2,
                                       uint32_t& r3, uint32_t addr) {
    asm volatile("ldmatrix.sync.aligned.m8n8.x4.shared.b16 {%0,%1,%2,%3}, [%4];"
                 : "=r"(r0), "=r"(r1), "=r"(r2), "=r"(r3) : "r"(addr));
}

__device__ __forceinline__ void imma16832(int* c, uint32_t a0, uint32_t a1,
                                          uint32_t a2, uint32_t a3,
                                          uint32_t b0, uint32_t b1) {
    asm volatile(
        "mma.sync.aligned.m16n8k32.row.col.s32.s8.s8.s32 "
        "{%0,%1,%2,%3}, {%4,%5,%6,%7}, {%8,%9}, {%0,%1,%2,%3};"
        : "+r"(c[0]), "+r"(c[1]), "+r"(c[2]), "+r"(c[3])
        : "r"(a0), "r"(a1), "r"(a2), "r"(a3), "r"(b0), "r"(b1));
}

__device__ __forceinline__ void lse_merge(float& m, float& s, float om, float os) {
    float M = fmaxf(m, om);
    s = s * __expf(m - M) + os * __expf(om - M);
    m = M;
}

// ============================================================================
// Kernel 1: L2-normalize rows + int8 quantize (per-row max-abs scale)
// ============================================================================
__global__ void __launch_bounds__(128) quantize_kernel(const float* __restrict__ src, int which) {
    int8_t* dst = which ? g_b_q : g_a_q;
    float* sc = which ? g_sb : g_sa20;
    int row = blockIdx.x;
    int t = threadIdx.x;
    const float4* s4 = (const float4*)src + (size_t)row * (DIM / 4);
    float4 v0 = s4[t];
    float4 v1 = s4[t + 128];
    float ss = v0.x * v0.x + v0.y * v0.y + v0.z * v0.z + v0.w * v0.w
             + v1.x * v1.x + v1.y * v1.y + v1.z * v1.z + v1.w * v1.w;
    float ma = fmaxf(fmaxf(fmaxf(fabsf(v0.x), fabsf(v0.y)), fmaxf(fabsf(v0.z), fabsf(v0.w))),
                     fmaxf(fmaxf(fabsf(v1.x), fabsf(v1.y)), fmaxf(fabsf(v1.z), fabsf(v1.w))));
    #pragma unroll
    for (int o = 16; o; o >>= 1) {
        ss += __shfl_xor_sync(0xffffffffu, ss, o);
        ma = fmaxf(ma, __shfl_xor_sync(0xffffffffu, ma, o));
    }
    __shared__ float wss[4], wma[4];
    if ((t & 31) == 0) { wss[t >> 5] = ss; wma[t >> 5] = ma; }
    __syncthreads();
    float inv = rsqrtf(wss[0] + wss[1] + wss[2] + wss[3]);
    float maxraw = fmaxf(fmaxf(wma[0], wma[1]), fmaxf(wma[2], wma[3]));
    float qs = 127.0f / maxraw;                      // raw value -> int8 (norm cancels)
    float sa = maxraw * inv * (1.0f / 127.0f);       // dequant scale on normalized row
    if (t == 0) sc[row] = which ? sa : LOSS_SCALE * sa;

    uint32_t p0 = ((uint32_t)(uint8_t)(int8_t)__float2int_rn(v0.x * qs))
                | ((uint32_t)(uint8_t)(int8_t)__float2int_rn(v0.y * qs) << 8)
                | ((uint32_t)(uint8_t)(int8_t)__float2int_rn(v0.z * qs) << 16)
                | ((uint32_t)(uint8_t)(int8_t)__float2int_rn(v0.w * qs) << 24);
    uint32_t p1 = ((uint32_t)(uint8_t)(int8_t)__float2int_rn(v1.x * qs))
                | ((uint32_t)(uint8_t)(int8_t)__float2int_rn(v1.y * qs) << 8)
                | ((uint32_t)(uint8_t)(int8_t)__float2int_rn(v1.z * qs) << 16)
                | ((uint32_t)(uint8_t)(int8_t)__float2int_rn(v1.w * qs) << 24);
    uint32_t* drow = (uint32_t*)(dst + (size_t)row * DIM);
    drow[t] = p0;
    drow[128 + t] = p1;
}

// ============================================================================
// Kernel 2: positive logits (exact fp32)
// ============================================================================
__global__ void __launch_bounds__(128) pos_kernel(const float* __restrict__ a,
                                                  const float* __restrict__ b) {
    int row = blockIdx.x;
    int t = threadIdx.x;
    const float4* a4 = (const float4*)a + (size_t)row * (DIM / 4);
    const float4* b4 = (const float4*)b + (size_t)row * (DIM / 4);
    float4 x0 = a4[t], x1 = a4[t + 128];
    float4 y0 = b4[t], y1 = b4[t + 128];
    float acc = x0.x * y0.x + x0.y * y0.y + x0.z * y0.z + x0.w * y0.w
              + x1.x * y1.x + x1.y * y1.y + x1.z * y1.z + x1.w * y1.w;
    float na = x0.x * x0.x + x0.y * x0.y + x0.z * x0.z + x0.w * x0.w
             + x1.x * x1.x + x1.y * x1.y + x1.z * x1.z + x1.w * x1.w;
    float nb = y0.x * y0.x + y0.y * y0.y + y0.z * y0.z + y0.w * y0.w
             + y1.x * y1.x + y1.y * y1.y + y1.z * y1.z + y1.w * y1.w;
    #pragma unroll
    for (int o = 16; o; o >>= 1) {
        acc += __shfl_xor_sync(0xffffffffu, acc, o);
        na += __shfl_xor_sync(0xffffffffu, na, o);
        nb += __shfl_xor_sync(0xffffffffu, nb, o);
    }
    __shared__ float wa[4], wn1[4], wn2[4];
    if ((t & 31) == 0) { wa[t >> 5] = acc; wn1[t >> 5] = na; wn2[t >> 5] = nb; }
    __syncthreads();
    if (t == 0) {
        float d = wa[0] + wa[1] + wa[2] + wa[3];
        float ia = rsqrtf(wn1[0] + wn1[1] + wn1[2] + wn1[3]);
        float ib = rsqrtf(wn2[0] + wn2[1] + wn2[2] + wn2[3]);
        g_pos[row] = LOSS_SCALE * d * ia * ib;
    }
}

// ============================================================================
// Kernel 3: fused int8 GEMM (mma.sync IMMA k32) + online row LSE
//   CTA: 128x256 tile, 256 threads, warp grid 2(m) x 4(n), warp tile 64x64.
// ============================================================================
__global__ void __launch_bounds__(THREADS, 1) gemm_lse_kernel() {
    extern __shared__ char sm[];
    uint32_t sb = smem_to_u32(sm);

    int t = threadIdx.x;
    int lane = t & 31;
    int w = t >> 5;
    int wm = w >> 2;             // 0..1
    int wn = w & 3;              // 0..3

    int rb = blockIdx.x / NSPLIT;
    int sp = blockIdx.x % NSPLIT;
    int col_base = sp * (BB / NSPLIT);

    float* red = (float*)(sm + SM_RED);          // [4][128][2]
    float* rowstate = (float*)(sm + SM_ROW);     // [128][2]
    if (t < 128) { rowstate[2 * t] = -1e30f; rowstate[2 * t + 1] = 0.f; }

    const char* a_gbase = (const char*)(g_a_q + (size_t)(rb * TM) * DIM);
    const char* b_gbase = (const char*)(g_b_q + (size_t)col_base * DIM);

    // per-thread row dequant scales (constant across chunks): rows of c0/c1 (h=0)
    // and c2/c3 (h=1) pairs
    float sav[4][2];
    #pragma unroll
    for (int mt = 0; mt < 4; mt++)
        #pragma unroll
        for (int h = 0; h < 2; h++)
            sav[mt][h] = g_sa20[rb * TM + wm * 64 + mt * 16 + h * 8 + (lane >> 2)];

    int acc[4][8][4];
    #pragma unroll
    for (int mt = 0; mt < 4; mt++)
        #pragma unroll
        for (int nt = 0; nt < 8; nt++)
            #pragma unroll
            for (int j = 0; j < 4; j++) acc[mt][nt][j] = 0;

    // --- issue one pipeline stage's cp.asyncs ---
    // A: 128 rows x 4 segs = 512 x 16B; B: 256 rows x 4 segs = 1024 x 16B
    auto issue = [&](int g) {
        if (g < TOTAL_STAGES) {
            int chunk = g >> 4;
            int kc = g & 15;
            int buf = g % STAGES;
            uint32_t sa = sb + SM_A(buf);
            uint32_t sbB = sb + SM_B(buf);
            size_t koff = (size_t)kc * TKS;
            size_t b_row0 = (size_t)chunk * TN;
            #pragma unroll
            for (int i = 0; i < 2; i++) {
                int c = t + i * THREADS;
                int row = c >> 2, seg = c & 3;
                cp_async16(sa + row * PITCH_B + seg * 16,
                           a_gbase + (size_t)row * DIM + koff + seg * 16);
            }
            #pragma unroll
            for (int i = 0; i < 4; i++) {
                int c = t + i * THREADS;
                int row = c >> 2, seg = c & 3;
                cp_async16(sbB + row * PITCH_B + seg * 16,
                           b_gbase + (b_row0 + row) * (size_t)DIM + koff + seg * 16);
            }
        }
        CP_COMMIT();
    };

    #pragma unroll
    for (int s = 0; s < STAGES - 1; s++) issue(s);

    for (int g = 0; g < TOTAL_STAGES; g++) {
        CP_WAIT(STAGES - 2);
        __syncthreads();
        issue(g + STAGES - 1);

        int buf = g % STAGES;
        // A frags: 16 rows per mt; lanes 0-15: rows, lanes 16-31: +16B k-half
        uint32_t saA = sb + SM_A(buf)
                     + (uint32_t)(wm * 64 + (lane & 15)) * PITCH_B
                     + ((lane >> 4) * 16);
        // B frags: nt-pair per ldm_x4 (16 n-rows); (lane>>4)&1 -> odd nt (+8 rows),
        // (lane>>3)&1 -> k-half (+16B)
        uint32_t sbF = sb + SM_B(buf)
                     + (uint32_t)(wn * 64 + ((lane >> 4) & 1) * 8 + (lane & 7)) * PITCH_B
                     + (((lane >> 3) & 1) * 16);

        #pragma unroll
        for (int kk = 0; kk < 2; kk++) {            // 2 x k32 per 64B stage
            uint32_t a0[4], a1[4], a2[4], a3[4];
            uint32_t b0[8], b1[8];
            #pragma unroll
            for (int mt = 0; mt < 4; mt++)
                ldm_x4(a0[mt], a1[mt], a2[mt], a3[mt],
                       saA + mt * 16 * PITCH_B + kk * 32);
            #pragma unroll
            for (int p = 0; p < 4; p++)
                ldm_x4(b0[2 * p], b1[2 * p], b0[2 * p + 1], b1[2 * p + 1],
                       sbF + p * 16 * PITCH_B + kk * 32);
            #pragma unroll
            for (int mt = 0; mt < 4; mt++)
                #pragma unroll
                for (int nt = 0; nt < 8; nt++)
                    imma16832(acc[mt][nt], a0[mt], a1[mt], a2[mt], a3[mt],
                              b0[nt], b1[nt]);
        }

        if ((g & 15) == 15) {
            // ---- flash-LSE epilogue for this 256-col chunk ----
            int chunk = g >> 4;
            const float* sbp = g_sb + col_base + chunk * TN + wn * 64 + (lane & 3) * 2;
            float sbv[8][2];
            #pragma unroll
            for (int nt = 0; nt < 8; nt++) {
                sbv[nt][0] = sbp[nt * 8];
                sbv[nt][1] = sbp[nt * 8 + 1];
            }
            #pragma unroll
            for (int mt = 0; mt < 4; mt++) {
                #pragma unroll
                for (int h = 0; h < 2; h++) {
                    float rs = sav[mt][h];
                    float m = -1e30f;
                    #pragma unroll
                    for (int nt = 0; nt < 8; nt++) {
                        #pragma unroll
                        for (int j = 0; j < 2; j++) {
                            float v = (float)acc[mt][nt][2 * h + j] * rs * sbv[nt][j];
                            acc[mt][nt][2 * h + j] = __float_as_int(v);  // stash
                            m = fmaxf(m, v);
                        }
                    }
                    float s = 0.f;
                    #pragma unroll
                    for (int nt = 0; nt < 8; nt++) {
                        s += __expf(__int_as_float(acc[mt][nt][2 * h]) - m);
                        s += __expf(__int_as_float(acc[mt][nt][2 * h + 1]) - m);
                    }
                    // quad reduce (lanes xor 1,2 share the same output row)
                    #pragma unroll
                    for (int off = 1; off <= 2; off <<= 1) {
                        float om = __shfl_xor_sync(0xffffffffu, m, off);
                        float os = __shfl_xor_sync(0xffffffffu, s, off);
                        lse_merge(m, s, om, os);
                    }
                    if ((lane & 3) == 0) {
                        int row = wm * 64 + mt * 16 + h * 8 + (lane >> 2);
                        red[(wn * 128 + row) * 2] = m;
                        red[(wn * 128 + row) * 2 + 1] = s;
                    }
                    #pragma unroll
                    for (int nt = 0; nt < 8; nt++) {
                        acc[mt][nt][2 * h] = 0;
                        acc[mt][nt][2 * h + 1] = 0;
                    }
                }
            }
            __syncthreads();
            if (t < 128) {
                float m = rowstate[2 * t], s = rowstate[2 * t + 1];
                #pragma unroll
                for (int cw = 0; cw < 4; cw++)
                    lse_merge(m, s, red[(cw * 128 + t) * 2], red[(cw * 128 + t) * 2 + 1]);
                rowstate[2 * t] = m;
                rowstate[2 * t + 1] = s;
            }
            // next loop iteration's __syncthreads orders red reuse
        }
    }

    __syncthreads();
    if (t < 128) {
        int row_g = rb * TM + t;
        g_pm[row_g * NSPLIT + sp] = rowstate[2 * t];
        g_ps[row_g * NSPLIT + sp] = rowstate[2 * t + 1];
    }
}

// ============================================================================
// Kernel 4/5: deterministic LSE combine + mean
// ============================================================================
__global__ void __launch_bounds__(128) combine_kernel() {
    int row = blockIdx.x * 128 + threadIdx.x;
    float M = -1e30f;
    float mv[NSPLIT], sv[NSPLIT];
    #pragma unroll
    for (int sp = 0; sp < NSPLIT; sp++) {
        mv[sp] = g_pm[row * NSPLIT + sp];
        sv[sp] = g_ps[row * NSPLIT + sp];
        M = fmaxf(M, mv[sp]);
    }
    float S = 0.f;
    #pragma unroll
    for (int sp = 0; sp < NSPLIT; sp++) S += sv[sp] * __expf(mv[sp] - M);
    float li = M + logf(S) - g_pos[row];
    #pragma unroll
    for (int o = 16; o; o >>= 1) li += __shfl_xor_sync(0xffffffffu, li, o);
    __shared__ float ws[4];
    if ((threadIdx.x & 31) == 0) ws[threadIdx.x >> 5] = li;
    __syncthreads();
    if (threadIdx.x == 0) g_part[blockIdx.x] = ws[0] + ws[1] + ws[2] + ws[3];
}

__global__ void __launch_bounds__(64) final_kernel(float* __restrict__ out) {
    float v = g_part[threadIdx.x];
    #pragma unroll
    for (int o = 16; o; o >>= 1) v += __shfl_xor_sync(0xffffffffu, v, o);
    __shared__ float ws[2];
    if ((threadIdx.x & 31) == 0) ws[threadIdx.x >> 5] = v;
    __syncthreads();
    if (threadIdx.x == 0) out[0] = (ws[0] + ws[1]) * (1.0f / (float)BA);
}

// ============================================================================
// Launch
// ============================================================================
extern "C" void kernel_launch(void* const* d_in, const int* in_sizes, int n_in,
                              void* d_out, int out_size) {
    (void)in_sizes; (void)n_in; (void)out_size;
    const float* a = (const float*)d_in[0];
    const float* b = (const float*)d_in[1];
    float* out = (float*)d_out;

    cudaFuncSetAttribute(gemm_lse_kernel,
                         cudaFuncAttributeMaxDynamicSharedMemorySize, SMEM_TOTAL);

    quantize_kernel<<<BA, 128>>>(a, 0);
    quantize_kernel<<<BB, 128>>>(b, 1);
    pos_kernel<<<BA, 128>>>(a, b);
    gemm_lse_kernel<<<ROWBLOCKS * NSPLIT, THREADS, SMEM_TOTAL>>>();
    combine_kernel<<<ROWBLOCKS, 128>>>();
    final_kernel<<<1, 64>>>(out);
}

// round 10
// speedup vs baseline: 2.3924x; 1.2188x over previous
#include <cuda_runtime.h>
#include <cuda_bf16.h>
#include <stdint.h>

// ============================================================================
// Problem constants
// ============================================================================
#define BA 8192
#define BB 16384
#define DIM 1024
#define LOSS_SCALE 20.0f

#define TM 128            // CTA rows
#define TN 256            // CTA cols per chunk
#define TKS 128           // K elems (bytes) per pipeline stage
#define STAGES 2
#define NSPLIT 2          // column splits per row-block
#define CHUNKS (BB / NSPLIT / TN)     // 32 chunks of 256 cols per CTA
#define KSTAGES (DIM / TKS)           // 8 k-stages per chunk
#define TOTAL_STAGES (CHUNKS * KSTAGES)  // 256
#define ROWBLOCKS (BA / TM)           // 64
#define THREADS 256

// ============================================================================
// Device scratch
// ============================================================================
__device__ __align__(128) int8_t g_a_q[(size_t)BA * DIM];   // 8 MB
__device__ __align__(128) int8_t g_b_q[(size_t)BB * DIM];   // 16 MB
__device__ float g_sa20[BA];   // 20 * per-row dequant scale for A
__device__ float g_sb[BB];     // per-row dequant scale for B
__device__ float g_pos[BA];
__device__ float g_pm[BA * NSPLIT];
__device__ float g_ps[BA * NSPLIT];
__device__ float g_part[ROWBLOCKS];

// ============================================================================
// SMEM layout (dynamic). int8 rows: 128 data bytes + 16 pad = 144 B pitch.
// 8-row ldmatrix phases hit {0,16,32,...,112} mod 128 -> conflict-free.
// ============================================================================
#define PITCH_B 144
#define A_STAGE_BYTES (128 * PITCH_B)        // 18432
#define B_STAGE_BYTES (256 * PITCH_B)        // 36864
#define SM_A(stg) ((stg) * A_STAGE_BYTES)
#define SM_B(stg) (STAGES * A_STAGE_BYTES + (stg) * B_STAGE_BYTES)
#define SM_RED (STAGES * (A_STAGE_BYTES + B_STAGE_BYTES))  // float red[4][128][2]
#define SM_ROW (SM_RED + 4 * 128 * 2 * 4)                  // float rowstate[128][2]
#define SMEM_TOTAL (SM_ROW + 128 * 2 * 4)                  // 115712 B

// ============================================================================
// PTX helpers
// ============================================================================
__device__ __forceinline__ uint32_t smem_to_u32(const void* p) {
    uint32_t a;
    asm("{ .reg .u64 t; cvta.to.shared.u64 t, %1; cvt.u32.u64 %0, t; }"
        : "=r"(a) : "l"(p));
    return a;
}

__device__ __forceinline__ void cp_async16(uint32_t s, const void* g) {
    asm volatile("cp.async.cg.shared.global [%0], [%1], 16;"
                 :: "r"(s), "l"(g) : "memory");
}
#define CP_COMMIT() asm volatile("cp.async.commit_group;" ::: "memory")
#define CP_WAIT(n)  asm volatile("cp.async.wait_group %0;" :: "n"(n) : "memory")

__device__ __forceinline__ void ldm_x4(uint32_t& r0, uint32_t& r1, uint32_t& r2,
                                       uint32_t& r3, uint32_t addr) {
    asm volatile("ldmatrix.sync.aligned.m8n8.x4.shared.b16 {%0,%1,%2,%3}, [%4];"
                 : "=r"(r0), "=r"(r1), "=r"(r2), "=r"(r3) : "r"(addr));
}

__device__ __forceinline__ void imma16832(int* c, uint32_t a0, uint32_t a1,
                                          uint32_t a2, uint32_t a3,
                                          uint32_t b0, uint32_t b1) {
    asm volatile(
        "mma.sync.aligned.m16n8k32.row.col.s32.s8.s8.s32 "
        "{%0,%1,%2,%3}, {%4,%5,%6,%7}, {%8,%9}, {%0,%1,%2,%3};"
        : "+r"(c[0]), "+r"(c[1]), "+r"(c[2]), "+r"(c[3])
        : "r"(a0), "r"(a1), "r"(a2), "r"(a3), "r"(b0), "r"(b1));
}

__device__ __forceinline__ void lse_merge(float& m, float& s, float om, float os) {
    float M = fmaxf(m, om);
    s = s * __expf(m - M) + os * __expf(om - M);
    m = M;
}

// ============================================================================
// Kernel 1: L2-normalize rows + int8 quantize (per-row max-abs scale)
// ============================================================================
__global__ void __launch_bounds__(128) quantize_kernel(const float* __restrict__ src, int which) {
    int8_t* dst = which ? g_b_q : g_a_q;
    float* sc = which ? g_sb : g_sa20;
    int row = blockIdx.x;
    int t = threadIdx.x;
    const float4* s4 = (const float4*)src + (size_t)row * (DIM / 4);
    float4 v0 = s4[t];
    float4 v1 = s4[t + 128];
    float ss = v0.x * v0.x + v0.y * v0.y + v0.z * v0.z + v0.w * v0.w
             + v1.x * v1.x + v1.y * v1.y + v1.z * v1.z + v1.w * v1.w;
    float ma = fmaxf(fmaxf(fmaxf(fabsf(v0.x), fabsf(v0.y)), fmaxf(fabsf(v0.z), fabsf(v0.w))),
                     fmaxf(fmaxf(fabsf(v1.x), fabsf(v1.y)), fmaxf(fabsf(v1.z), fabsf(v1.w))));
    #pragma unroll
    for (int o = 16; o; o >>= 1) {
        ss += __shfl_xor_sync(0xffffffffu, ss, o);
        ma = fmaxf(ma, __shfl_xor_sync(0xffffffffu, ma, o));
    }
    __shared__ float wss[4], wma[4];
    if ((t & 31) == 0) { wss[t >> 5] = ss; wma[t >> 5] = ma; }
    __syncthreads();
    float inv = rsqrtf(wss[0] + wss[1] + wss[2] + wss[3]);
    float maxraw = fmaxf(fmaxf(wma[0], wma[1]), fmaxf(wma[2], wma[3]));
    float qs = 127.0f / maxraw;                      // raw value -> int8 (norm cancels)
    float sa = maxraw * inv * (1.0f / 127.0f);       // dequant scale on normalized row
    if (t == 0) sc[row] = which ? sa : LOSS_SCALE * sa;

    uint32_t p0 = ((uint32_t)(uint8_t)(int8_t)__float2int_rn(v0.x * qs))
                | ((uint32_t)(uint8_t)(int8_t)__float2int_rn(v0.y * qs) << 8)
                | ((uint32_t)(uint8_t)(int8_t)__float2int_rn(v0.z * qs) << 16)
                | ((uint32_t)(uint8_t)(int8_t)__float2int_rn(v0.w * qs) << 24);
    uint32_t p1 = ((uint32_t)(uint8_t)(int8_t)__float2int_rn(v1.x * qs))
                | ((uint32_t)(uint8_t)(int8_t)__float2int_rn(v1.y * qs) << 8)
                | ((uint32_t)(uint8_t)(int8_t)__float2int_rn(v1.z * qs) << 16)
                | ((uint32_t)(uint8_t)(int8_t)__float2int_rn(v1.w * qs) << 24);
    uint32_t* drow = (uint32_t*)(dst + (size_t)row * DIM);
    drow[t] = p0;
    drow[128 + t] = p1;
}

// ============================================================================
// Kernel 2: positive logits (exact fp32)
// ============================================================================
__global__ void __launch_bounds__(128) pos_kernel(const float* __restrict__ a,
                                                  const float* __restrict__ b) {
    int row = blockIdx.x;
    int t = threadIdx.x;
    const float4* a4 = (const float4*)a + (size_t)row * (DIM / 4);
    const float4* b4 = (const float4*)b + (size_t)row * (DIM / 4);
    float4 x0 = a4[t], x1 = a4[t + 128];
    float4 y0 = b4[t], y1 = b4[t + 128];
    float acc = x0.x * y0.x + x0.y * y0.y + x0.z * y0.z + x0.w * y0.w
              + x1.x * y1.x + x1.y * y1.y + x1.z * y1.z + x1.w * y1.w;
    float na = x0.x * x0.x + x0.y * x0.y + x0.z * x0.z + x0.w * x0.w
             + x1.x * x1.x + x1.y * x1.y + x1.z * x1.z + x1.w * x1.w;
    float nb = y0.x * y0.x + y0.y * y0.y + y0.z * y0.z + y0.w * y0.w
             + y1.x * y1.x + y1.y * y1.y + y1.z * y1.z + y1.w * y1.w;
    #pragma unroll
    for (int o = 16; o; o >>= 1) {
        acc += __shfl_xor_sync(0xffffffffu, acc, o);
        na += __shfl_xor_sync(0xffffffffu, na, o);
        nb += __shfl_xor_sync(0xffffffffu, nb, o);
    }
    __shared__ float wa[4], wn1[4], wn2[4];
    if ((t & 31) == 0) { wa[t >> 5] = acc; wn1[t >> 5] = na; wn2[t >> 5] = nb; }
    __syncthreads();
    if (t == 0) {
        float d = wa[0] + wa[1] + wa[2] + wa[3];
        float ia = rsqrtf(wn1[0] + wn1[1] + wn1[2] + wn1[3]);
        float ib = rsqrtf(wn2[0] + wn2[1] + wn2[2] + wn2[3]);
        g_pos[row] = LOSS_SCALE * d * ia * ib;
    }
}

// ============================================================================
// Kernel 3: fused int8 GEMM (mma.sync IMMA k32) + online row LSE
//   CTA: 128x256 tile, 256 threads, warp grid 2(m) x 4(n), warp tile 64x64.
//   Stage = full 128-byte k-slab (4 kk iterations), matching R8's 100%-eff shape.
// ============================================================================
__global__ void __launch_bounds__(THREADS, 1) gemm_lse_kernel() {
    extern __shared__ char sm[];
    uint32_t sb = smem_to_u32(sm);

    int t = threadIdx.x;
    int lane = t & 31;
    int w = t >> 5;
    int wm = w >> 2;             // 0..1
    int wn = w & 3;              // 0..3

    int rb = blockIdx.x / NSPLIT;
    int sp = blockIdx.x % NSPLIT;
    int col_base = sp * (BB / NSPLIT);

    float* red = (float*)(sm + SM_RED);          // [4][128][2]
    float* rowstate = (float*)(sm + SM_ROW);     // [128][2]
    if (t < 128) { rowstate[2 * t] = -1e30f; rowstate[2 * t + 1] = 0.f; }

    const char* a_gbase = (const char*)(g_a_q + (size_t)(rb * TM) * DIM);
    const char* b_gbase = (const char*)(g_b_q + (size_t)col_base * DIM);

    // per-thread row dequant scales (constant across chunks)
    float sav[4][2];
    #pragma unroll
    for (int mt = 0; mt < 4; mt++)
        #pragma unroll
        for (int h = 0; h < 2; h++)
            sav[mt][h] = g_sa20[rb * TM + wm * 64 + mt * 16 + h * 8 + (lane >> 2)];

    int acc[4][8][4];
    #pragma unroll
    for (int mt = 0; mt < 4; mt++)
        #pragma unroll
        for (int nt = 0; nt < 8; nt++)
            #pragma unroll
            for (int j = 0; j < 4; j++) acc[mt][nt][j] = 0;

    // --- issue one pipeline stage's cp.asyncs ---
    // A: 128 rows x 8 segs = 1024 x 16B; B: 256 rows x 8 segs = 2048 x 16B
    auto issue = [&](int g) {
        if (g < TOTAL_STAGES) {
            int chunk = g >> 3;
            int kc = g & 7;
            int buf = g % STAGES;
            uint32_t sa = sb + SM_A(buf);
            uint32_t sbB = sb + SM_B(buf);
            size_t koff = (size_t)kc * TKS;
            size_t b_row0 = (size_t)chunk * TN;
            #pragma unroll
            for (int i = 0; i < 4; i++) {
                int c = t + i * THREADS;
                int row = c >> 3, seg = c & 7;
                cp_async16(sa + row * PITCH_B + seg * 16,
                           a_gbase + (size_t)row * DIM + koff + seg * 16);
            }
            #pragma unroll
            for (int i = 0; i < 8; i++) {
                int c = t + i * THREADS;
                int row = c >> 3, seg = c & 7;
                cp_async16(sbB + row * PITCH_B + seg * 16,
                           b_gbase + (b_row0 + row) * (size_t)DIM + koff + seg * 16);
            }
        }
        CP_COMMIT();
    };

    #pragma unroll
    for (int s = 0; s < STAGES - 1; s++) issue(s);

    for (int g = 0; g < TOTAL_STAGES; g++) {
        CP_WAIT(STAGES - 2);
        __syncthreads();
        issue(g + STAGES - 1);

        int buf = g % STAGES;
        // A frags: 16 rows per mt; lanes 0-15: rows, lanes 16-31: +16B k-half
        uint32_t saA = sb + SM_A(buf)
                     + (uint32_t)(wm * 64 + (lane & 15)) * PITCH_B
                     + ((lane >> 4) * 16);
        // B frags: nt-pair per ldm_x4 (16 n-rows); (lane>>4)&1 -> odd nt (+8 rows),
        // (lane>>3)&1 -> k-half (+16B)
        uint32_t sbF = sb + SM_B(buf)
                     + (uint32_t)(wn * 64 + ((lane >> 4) & 1) * 8 + (lane & 7)) * PITCH_B
                     + (((lane >> 3) & 1) * 16);

        #pragma unroll
        for (int kk = 0; kk < 4; kk++) {            // 4 x k32 per 128B stage
            uint32_t a0[4], a1[4], a2[4], a3[4];
            uint32_t b0[8], b1[8];
            #pragma unroll
            for (int mt = 0; mt < 4; mt++)
                ldm_x4(a0[mt], a1[mt], a2[mt], a3[mt],
                       saA + mt * 16 * PITCH_B + kk * 32);
            #pragma unroll
            for (int p = 0; p < 4; p++)
                ldm_x4(b0[2 * p], b1[2 * p], b0[2 * p + 1], b1[2 * p + 1],
                       sbF + p * 16 * PITCH_B + kk * 32);
            #pragma unroll
            for (int mt = 0; mt < 4; mt++)
                #pragma unroll
                for (int nt = 0; nt < 8; nt++)
                    imma16832(acc[mt][nt], a0[mt], a1[mt], a2[mt], a3[mt],
                              b0[nt], b1[nt]);
        }

        if ((g & 7) == 7) {
            // ---- flash-LSE epilogue for this 256-col chunk ----
            int chunk = g >> 3;
            const float* sbp = g_sb + col_base + chunk * TN + wn * 64 + (lane & 3) * 2;
            float sbv[8][2];
            #pragma unroll
            for (int nt = 0; nt < 8; nt++) {
                sbv[nt][0] = sbp[nt * 8];
                sbv[nt][1] = sbp[nt * 8 + 1];
            }
            #pragma unroll
            for (int mt = 0; mt < 4; mt++) {
                #pragma unroll
                for (int h = 0; h < 2; h++) {
                    float rs = sav[mt][h];
                    float m = -1e30f;
                    #pragma unroll
                    for (int nt = 0; nt < 8; nt++) {
                        #pragma unroll
                        for (int j = 0; j < 2; j++) {
                            float v = (float)acc[mt][nt][2 * h + j] * rs * sbv[nt][j];
                            acc[mt][nt][2 * h + j] = __float_as_int(v);  // stash
                            m = fmaxf(m, v);
                        }
                    }
                    float s = 0.f;
                    #pragma unroll
                    for (int nt = 0; nt < 8; nt++) {
                        s += __expf(__int_as_float(acc[mt][nt][2 * h]) - m);
                        s += __expf(__int_as_float(acc[mt][nt][2 * h + 1]) - m);
                    }
                    // quad reduce (lanes xor 1,2 share the same output row)
                    #pragma unroll
                    for (int off = 1; off <= 2; off <<= 1) {
                        float om = __shfl_xor_sync(0xffffffffu, m, off);
                        float os = __shfl_xor_sync(0xffffffffu, s, off);
                        lse_merge(m, s, om, os);
                    }
                    if ((lane & 3) == 0) {
                        int row = wm * 64 + mt * 16 + h * 8 + (lane >> 2);
                        red[(wn * 128 + row) * 2] = m;
                        red[(wn * 128 + row) * 2 + 1] = s;
                    }
                    #pragma unroll
                    for (int nt = 0; nt < 8; nt++) {
                        acc[mt][nt][2 * h] = 0;
                        acc[mt][nt][2 * h + 1] = 0;
                    }
                }
            }
            __syncthreads();
            if (t < 128) {
                float m = rowstate[2 * t], s = rowstate[2 * t + 1];
                #pragma unroll
                for (int cw = 0; cw < 4; cw++)
                    lse_merge(m, s, red[(cw * 128 + t) * 2], red[(cw * 128 + t) * 2 + 1]);
                rowstate[2 * t] = m;
                rowstate[2 * t + 1] = s;
            }
            // next loop iteration's __syncthreads orders red reuse
        }
    }

    __syncthreads();
    if (t < 128) {
        int row_g = rb * TM + t;
        g_pm[row_g * NSPLIT + sp] = rowstate[2 * t];
        g_ps[row_g * NSPLIT + sp] = rowstate[2 * t + 1];
    }
}

// ============================================================================
// Kernel 4/5: deterministic LSE combine + mean
// ============================================================================
__global__ void __launch_bounds__(128) combine_kernel() {
    int row = blockIdx.x * 128 + threadIdx.x;
    float M = -1e30f;
    float mv[NSPLIT], sv[NSPLIT];
    #pragma unroll
    for (int sp = 0; sp < NSPLIT; sp++) {
        mv[sp] = g_pm[row * NSPLIT + sp];
        sv[sp] = g_ps[row * NSPLIT + sp];
        M = fmaxf(M, mv[sp]);
    }
    float S = 0.f;
    #pragma unroll
    for (int sp = 0; sp < NSPLIT; sp++) S += sv[sp] * __expf(mv[sp] - M);
    float li = M + logf(S) - g_pos[row];
    #pragma unroll
    for (int o = 16; o; o >>= 1) li += __shfl_xor_sync(0xffffffffu, li, o);
    __shared__ float ws[4];
    if ((threadIdx.x & 31) == 0) ws[threadIdx.x >> 5] = li;
    __syncthreads();
    if (threadIdx.x == 0) g_part[blockIdx.x] = ws[0] + ws[1] + ws[2] + ws[3];
}

__global__ void __launch_bounds__(64) final_kernel(float* __restrict__ out) {
    float v = g_part[threadIdx.x];
    #pragma unroll
    for (int o = 16; o; o >>= 1) v += __shfl_xor_sync(0xffffffffu, v, o);
    __shared__ float ws[2];
    if ((threadIdx.x & 31) == 0) ws[threadIdx.x >> 5] = v;
    __syncthreads();
    if (threadIdx.x == 0) out[0] = (ws[0] + ws[1]) * (1.0f / (float)BA);
}

// ============================================================================
// Launch
// ============================================================================
extern "C" void kernel_launch(void* const* d_in, const int* in_sizes, int n_in,
                              void* d_out, int out_size) {
    (void)in_sizes; (void)n_in; (void)out_size;
    const float* a = (const float*)d_in[0];
    const float* b = (const float*)d_in[1];
    float* out = (float*)d_out;

    cudaFuncSetAttribute(gemm_lse_kernel,
                         cudaFuncAttributeMaxDynamicSharedMemorySize, SMEM_TOTAL);

    quantize_kernel<<<BA, 128>>>(a, 0);
    quantize_kernel<<<BB, 128>>>(b, 1);
    pos_kernel<<<BA, 128>>>(a, b);
    gemm_lse_kernel<<<ROWBLOCKS * NSPLIT, THREADS, SMEM_TOTAL>>>();
    combine_kernel<<<ROWBLOCKS, 128>>>();
    final_kernel<<<1, 64>>>(out);
}

// round 11
// speedup vs baseline: 2.6497x; 1.1075x over previous
#include <cuda_runtime.h>
#include <cuda_bf16.h>
#include <stdint.h>

// ============================================================================
// Problem constants
// ============================================================================
#define BA 8192
#define BB 16384
#define DIM 1024
#define LOSS_SCALE 20.0f

#define TM 128            // item rows
#define TN 256            // item cols
#define TKS 128           // K bytes per pipeline stage
#define STAGES 2
#define KSTAGES (DIM / TKS)           // 8 stages per item
#define NCHUNK (BB / TN)              // 64 column chunks
#define ROWBLOCKS (BA / TM)           // 64
#define NITEMS (ROWBLOCKS * NCHUNK)   // 4096 work items
#define THREADS 256

// ============================================================================
// Device scratch
// ============================================================================
__device__ __align__(128) int8_t g_a_q[(size_t)BA * DIM];   // 8 MB
__device__ __align__(128) int8_t g_b_q[(size_t)BB * DIM];   // 16 MB
__device__ float g_sa20[BA];   // 20 * per-row dequant scale for A
__device__ float g_sb[BB];     // per-row dequant scale for B
__device__ float g_pos[BA];
__device__ float g_pm[NCHUNK * BA];   // transposed: [chunk][row]
__device__ float g_ps[NCHUNK * BA];
__device__ float g_part[ROWBLOCKS];
__device__ unsigned int g_ctr;

// ============================================================================
// SMEM layout. int8 rows: 128 data bytes + 16 pad = 144 B pitch.
// ============================================================================
#define PITCH_B 144
#define A_STAGE_BYTES (128 * PITCH_B)        // 18432
#define B_STAGE_BYTES (256 * PITCH_B)        // 36864
#define SM_A(stg) ((stg) * A_STAGE_BYTES)
#define SM_B(stg) (STAGES * A_STAGE_BYTES + (stg) * B_STAGE_BYTES)
#define SM_RED (STAGES * (A_STAGE_BYTES + B_STAGE_BYTES))  // float red[4][128][2]
#define SMEM_TOTAL (SM_RED + 4 * 128 * 2 * 4 + 32)         // ~114.8 KB

// ============================================================================
// PTX helpers
// ============================================================================
__device__ __forceinline__ uint32_t smem_to_u32(const void* p) {
    uint32_t a;
    asm("{ .reg .u64 t; cvta.to.shared.u64 t, %1; cvt.u32.u64 %0, t; }"
        : "=r"(a) : "l"(p));
    return a;
}

__device__ __forceinline__ void cp_async16(uint32_t s, const void* g) {
    asm volatile("cp.async.cg.shared.global [%0], [%1], 16;"
                 :: "r"(s), "l"(g) : "memory");
}
#define CP_COMMIT() asm volatile("cp.async.commit_group;" ::: "memory")
#define CP_WAIT(n)  asm volatile("cp.async.wait_group %0;" :: "n"(n) : "memory")

__device__ __forceinline__ void ldm_x4(uint32_t& r0, uint32_t& r1, uint32_t& r2,
                                       uint32_t& r3, uint32_t addr) {
    asm volatile("ldmatrix.sync.aligned.m8n8.x4.shared.b16 {%0,%1,%2,%3}, [%4];"
                 : "=r"(r0), "=r"(r1), "=r"(r2), "=r"(r3) : "r"(addr));
}

__device__ __forceinline__ void imma16832(int* c, uint32_t a0, uint32_t a1,
                                          uint32_t a2, uint32_t a3,
                                          uint32_t b0, uint32_t b1) {
    asm volatile(
        "mma.sync.aligned.m16n8k32.row.col.s32.s8.s8.s32 "
        "{%0,%1,%2,%3}, {%4,%5,%6,%7}, {%8,%9}, {%0,%1,%2,%3};"
        : "+r"(c[0]), "+r"(c[1]), "+r"(c[2]), "+r"(c[3])
        : "r"(a0), "r"(a1), "r"(a2), "r"(a3), "r"(b0), "r"(b1));
}

__device__ __forceinline__ void lse_merge(float& m, float& s, float om, float os) {
    float M = fmaxf(m, om);
    s = s * __expf(m - M) + os * __expf(om - M);
    m = M;
}

__global__ void reset_ctr_kernel(unsigned int v) { g_ctr = v; }

// ============================================================================
// Kernel 1a: quantize A + compute pos (reads both a and b rows once)
// ============================================================================
__global__ void __launch_bounds__(128) quantize_a_pos_kernel(const float* __restrict__ a,
                                                             const float* __restrict__ b) {
    int row = blockIdx.x;
    int t = threadIdx.x;
    const float4* a4 = (const float4*)a + (size_t)row * (DIM / 4);
    const float4* b4 = (const float4*)b + (size_t)row * (DIM / 4);
    float4 v0 = a4[t], v1 = a4[t + 128];
    float4 y0 = b4[t], y1 = b4[t + 128];
    float ss = v0.x * v0.x + v0.y * v0.y + v0.z * v0.z + v0.w * v0.w
             + v1.x * v1.x + v1.y * v1.y + v1.z * v1.z + v1.w * v1.w;
    float ma = fmaxf(fmaxf(fmaxf(fabsf(v0.x), fabsf(v0.y)), fmaxf(fabsf(v0.z), fabsf(v0.w))),
                     fmaxf(fmaxf(fabsf(v1.x), fabsf(v1.y)), fmaxf(fabsf(v1.z), fabsf(v1.w))));
    float dt = v0.x * y0.x + v0.y * y0.y + v0.z * y0.z + v0.w * y0.w
             + v1.x * y1.x + v1.y * y1.y + v1.z * y1.z + v1.w * y1.w;
    float nb = y0.x * y0.x + y0.y * y0.y + y0.z * y0.z + y0.w * y0.w
             + y1.x * y1.x + y1.y * y1.y + y1.z * y1.z + y1.w * y1.w;
    #pragma unroll
    for (int o = 16; o; o >>= 1) {
        ss += __shfl_xor_sync(0xffffffffu, ss, o);
        ma = fmaxf(ma, __shfl_xor_sync(0xffffffffu, ma, o));
        dt += __shfl_xor_sync(0xffffffffu, dt, o);
        nb += __shfl_xor_sync(0xffffffffu, nb, o);
    }
    __shared__ float wss[4], wma[4], wdt[4], wnb[4];
    if ((t & 31) == 0) { wss[t >> 5] = ss; wma[t >> 5] = ma; wdt[t >> 5] = dt; wnb[t >> 5] = nb; }
    __syncthreads();
    float sumsq = wss[0] + wss[1] + wss[2] + wss[3];
    float inv = rsqrtf(sumsq);
    float maxraw = fmaxf(fmaxf(wma[0], wma[1]), fmaxf(wma[2], wma[3]));
    float qs = 127.0f / maxraw;
    if (t == 0) {
        g_sa20[row] = LOSS_SCALE * maxraw * inv * (1.0f / 127.0f);
        float dot = wdt[0] + wdt[1] + wdt[2] + wdt[3];
        float ib = rsqrtf(wnb[0] + wnb[1] + wnb[2] + wnb[3]);
        g_pos[row] = LOSS_SCALE * dot * inv * ib;
    }
    uint32_t p0 = ((uint32_t)(uint8_t)(int8_t)__float2int_rn(v0.x * qs))
                | ((uint32_t)(uint8_t)(int8_t)__float2int_rn(v0.y * qs) << 8)
                | ((uint32_t)(uint8_t)(int8_t)__float2int_rn(v0.z * qs) << 16)
                | ((uint32_t)(uint8_t)(int8_t)__float2int_rn(v0.w * qs) << 24);
    uint32_t p1 = ((uint32_t)(uint8_t)(int8_t)__float2int_rn(v1.x * qs))
                | ((uint32_t)(uint8_t)(int8_t)__float2int_rn(v1.y * qs) << 8)
                | ((uint32_t)(uint8_t)(int8_t)__float2int_rn(v1.z * qs) << 16)
                | ((uint32_t)(uint8_t)(int8_t)__float2int_rn(v1.w * qs) << 24);
    uint32_t* drow = (uint32_t*)(g_a_q + (size_t)row * DIM);
    drow[t] = p0;
    drow[128 + t] = p1;
}

// ============================================================================
// Kernel 1b: quantize B
// ============================================================================
__global__ void __launch_bounds__(128) quantize_b_kernel(const float* __restrict__ src) {
    int row = blockIdx.x;
    int t = threadIdx.x;
    const float4* s4 = (const float4*)src + (size_t)row * (DIM / 4);
    float4 v0 = s4[t];
    float4 v1 = s4[t + 128];
    float ss = v0.x * v0.x + v0.y * v0.y + v0.z * v0.z + v0.w * v0.w
             + v1.x * v1.x + v1.y * v1.y + v1.z * v1.z + v1.w * v1.w;
    float ma = fmaxf(fmaxf(fmaxf(fabsf(v0.x), fabsf(v0.y)), fmaxf(fabsf(v0.z), fabsf(v0.w))),
                     fmaxf(fmaxf(fabsf(v1.x), fabsf(v1.y)), fmaxf(fabsf(v1.z), fabsf(v1.w))));
    #pragma unroll
    for (int o = 16; o; o >>= 1) {
        ss += __shfl_xor_sync(0xffffffffu, ss, o);
        ma = fmaxf(ma, __shfl_xor_sync(0xffffffffu, ma, o));
    }
    __shared__ float wss[4], wma[4];
    if ((t & 31) == 0) { wss[t >> 5] = ss; wma[t >> 5] = ma; }
    __syncthreads();
    float inv = rsqrtf(wss[0] + wss[1] + wss[2] + wss[3]);
    float maxraw = fmaxf(fmaxf(wma[0], wma[1]), fmaxf(wma[2], wma[3]));
    float qs = 127.0f / maxraw;
    if (t == 0) g_sb[row] = maxraw * inv * (1.0f / 127.0f);
    uint32_t p0 = ((uint32_t)(uint8_t)(int8_t)__float2int_rn(v0.x * qs))
                | ((uint32_t)(uint8_t)(int8_t)__float2int_rn(v0.y * qs) << 8)
                | ((uint32_t)(uint8_t)(int8_t)__float2int_rn(v0.z * qs) << 16)
                | ((uint32_t)(uint8_t)(int8_t)__float2int_rn(v0.w * qs) << 24);
    uint32_t p1 = ((uint32_t)(uint8_t)(int8_t)__float2int_rn(v1.x * qs))
                | ((uint32_t)(uint8_t)(int8_t)__float2int_rn(v1.y * qs) << 8)
                | ((uint32_t)(uint8_t)(int8_t)__float2int_rn(v1.z * qs) << 16)
                | ((uint32_t)(uint8_t)(int8_t)__float2int_rn(v1.w * qs) << 24);
    uint32_t* drow = (uint32_t*)(g_b_q + (size_t)row * DIM);
    drow[t] = p0;
    drow[128 + t] = p1;
}

// ============================================================================
// Kernel 2: persistent fused int8 GEMM (IMMA k32) + per-item LSE partials
//   Item = (rb, chunk): 128x256 tile over full K. Work stolen via g_ctr.
// ============================================================================
__global__ void __launch_bounds__(THREADS, 1) gemm_lse_kernel() {
    extern __shared__ char sm[];
    uint32_t sb = smem_to_u32(sm);

    int t = threadIdx.x;
    int lane = t & 31;
    int w = t >> 5;
    int wm = w >> 2;             // 0..1
    int wn = w & 3;              // 0..3

    float* red = (float*)(sm + SM_RED);          // [4][128][2]
    __shared__ int sm_next;

    int acc[4][8][4];
    #pragma unroll
    for (int mt = 0; mt < 4; mt++)
        #pragma unroll
        for (int nt = 0; nt < 8; nt++)
            #pragma unroll
            for (int j = 0; j < 4; j++) acc[mt][nt][j] = 0;

    // --- issue one stage of cp.asyncs for item `it`, k-chunk `kc`, buffer `buf`
    auto issue = [&](int it, int kc, int buf) {
        if (it < NITEMS) {
            int rb_ = it >> 6;
            int ch_ = it & 63;
            const char* ag = (const char*)g_a_q + (size_t)(rb_ * TM) * DIM;
            const char* bg = (const char*)g_b_q + (size_t)(ch_ * TN) * DIM;
            uint32_t sa = sb + SM_A(buf);
            uint32_t sbB = sb + SM_B(buf);
            size_t koff = (size_t)kc * TKS;
            #pragma unroll
            for (int i = 0; i < 4; i++) {
                int c = t + i * THREADS;
                int row = c >> 3, seg = c & 7;
                cp_async16(sa + row * PITCH_B + seg * 16,
                           ag + (size_t)row * DIM + koff + seg * 16);
            }
            #pragma unroll
            for (int i = 0; i < 8; i++) {
                int c = t + i * THREADS;
                int row = c >> 3, seg = c & 7;
                cp_async16(sbB + row * PITCH_B + seg * 16,
                           bg + (size_t)row * DIM + koff + seg * 16);
            }
        }
        CP_COMMIT();
    };

    int item = blockIdx.x;
    int ibuf = 0, cbuf = 0;
    issue(item, 0, ibuf); ibuf ^= 1;

    while (item < NITEMS) {
        int rb = item >> 6;
        int chunk = item & 63;

        // per-thread A row dequant scales for this row-block
        float sav[4][2];
        #pragma unroll
        for (int mt = 0; mt < 4; mt++)
            #pragma unroll
            for (int h = 0; h < 2; h++)
                sav[mt][h] = g_sa20[rb * TM + wm * 64 + mt * 16 + h * 8 + (lane >> 2)];

        for (int s = 0; s < KSTAGES; s++) {
            CP_WAIT(0);
            __syncthreads();
            if (s == 0 && t == 0) sm_next = (int)atomicAdd(&g_ctr, 1u);
            if (s < KSTAGES - 1) issue(item, s + 1, ibuf);
            else issue(sm_next, 0, ibuf);   // sm_next visible: written s0, synced s1
            ibuf ^= 1;

            // A frags: 16 rows per mt; lanes 0-15: rows, lanes 16-31: +16B k-half
            uint32_t saA = sb + SM_A(cbuf)
                         + (uint32_t)(wm * 64 + (lane & 15)) * PITCH_B
                         + ((lane >> 4) * 16);
            // B frags: nt-pair per ldm_x4 (16 n-rows)
            uint32_t sbF = sb + SM_B(cbuf)
                         + (uint32_t)(wn * 64 + ((lane >> 4) & 1) * 8 + (lane & 7)) * PITCH_B
                         + (((lane >> 3) & 1) * 16);
            cbuf ^= 1;

            #pragma unroll
            for (int kk = 0; kk < 4; kk++) {            // 4 x k32 per 128B stage
                uint32_t a0[4], a1[4], a2[4], a3[4];
                uint32_t b0[8], b1[8];
                #pragma unroll
                for (int mt = 0; mt < 4; mt++)
                    ldm_x4(a0[mt], a1[mt], a2[mt], a3[mt],
                           saA + mt * 16 * PITCH_B + kk * 32);
                #pragma unroll
                for (int p = 0; p < 4; p++)
                    ldm_x4(b0[2 * p], b1[2 * p], b0[2 * p + 1], b1[2 * p + 1],
                           sbF + p * 16 * PITCH_B + kk * 32);
                #pragma unroll
                for (int mt = 0; mt < 4; mt++)
                    #pragma unroll
                    for (int nt = 0; nt < 8; nt++)
                        imma16832(acc[mt][nt], a0[mt], a1[mt], a2[mt], a3[mt],
                                  b0[nt], b1[nt]);
            }

            if (s == KSTAGES - 1) {
                // ---- LSE epilogue for this item's 256 cols ----
                const float* sbp = g_sb + chunk * TN + wn * 64 + (lane & 3) * 2;
                float sbv[8][2];
                #pragma unroll
                for (int nt = 0; nt < 8; nt++) {
                    sbv[nt][0] = sbp[nt * 8];
                    sbv[nt][1] = sbp[nt * 8 + 1];
                }
                #pragma unroll
                for (int mt = 0; mt < 4; mt++) {
                    #pragma unroll
                    for (int h = 0; h < 2; h++) {
                        float rs = sav[mt][h];
                        float m = -1e30f;
                        #pragma unroll
                        for (int nt = 0; nt < 8; nt++) {
                            #pragma unroll
                            for (int j = 0; j < 2; j++) {
                                float v = (float)acc[mt][nt][2 * h + j] * rs * sbv[nt][j];
                                acc[mt][nt][2 * h + j] = __float_as_int(v);  // stash
                                m = fmaxf(m, v);
                            }
                        }
                        float ssum = 0.f;
                        #pragma unroll
                        for (int nt = 0; nt < 8; nt++) {
                            ssum += __expf(__int_as_float(acc[mt][nt][2 * h]) - m);
                            ssum += __expf(__int_as_float(acc[mt][nt][2 * h + 1]) - m);
                        }
                        // quad reduce (lanes xor 1,2 share the same output row)
                        #pragma unroll
                        for (int off = 1; off <= 2; off <<= 1) {
                            float om = __shfl_xor_sync(0xffffffffu, m, off);
                            float os = __shfl_xor_sync(0xffffffffu, ssum, off);
                            lse_merge(m, ssum, om, os);
                        }
                        if ((lane & 3) == 0) {
                            int row = wm * 64 + mt * 16 + h * 8 + (lane >> 2);
                            red[(wn * 128 + row) * 2] = m;
                            red[(wn * 128 + row) * 2 + 1] = ssum;
                        }
                        #pragma unroll
                        for (int nt = 0; nt < 8; nt++) {
                            acc[mt][nt][2 * h] = 0;
                            acc[mt][nt][2 * h + 1] = 0;
                        }
                    }
                }
                __syncthreads();
                if (t < 128) {
                    float m = red[2 * t], ssum = red[2 * t + 1];
                    #pragma unroll
                    for (int cw = 1; cw < 4; cw++)
                        lse_merge(m, ssum, red[(cw * 128 + t) * 2], red[(cw * 128 + t) * 2 + 1]);
                    int row = rb * TM + t;
                    g_pm[chunk * BA + row] = m;
                    g_ps[chunk * BA + row] = ssum;
                }
                // red[] not touched again until next item's epilogue (8 stages away)
            }
        }
        item = sm_next;
    }
    CP_WAIT(0);   // drain dangling empty commits
}

// ============================================================================
// Kernel 3/4: deterministic LSE combine + mean
// ============================================================================
__global__ void __launch_bounds__(128) combine_kernel() {
    int row = blockIdx.x * 128 + threadIdx.x;
    float M = g_pm[row], S = g_ps[row];
    #pragma unroll 4
    for (int c = 1; c < NCHUNK; c++)
        lse_merge(M, S, g_pm[c * BA + row], g_ps[c * BA + row]);
    float li = M + logf(S) - g_pos[row];
    #pragma unroll
    for (int o = 16; o; o >>= 1) li += __shfl_xor_sync(0xffffffffu, li, o);
    __shared__ float ws[4];
    if ((threadIdx.x & 31) == 0) ws[threadIdx.x >> 5] = li;
    __syncthreads();
    if (threadIdx.x == 0) g_part[blockIdx.x] = ws[0] + ws[1] + ws[2] + ws[3];
}

__global__ void __launch_bounds__(64) final_kernel(float* __restrict__ out) {
    float v = g_part[threadIdx.x];
    #pragma unroll
    for (int o = 16; o; o >>= 1) v += __shfl_xor_sync(0xffffffffu, v, o);
    __shared__ float ws[2];
    if ((threadIdx.x & 31) == 0) ws[threadIdx.x >> 5] = v;
    __syncthreads();
    if (threadIdx.x == 0) out[0] = (ws[0] + ws[1]) * (1.0f / (float)BA);
}

// ============================================================================
// Launch
// ============================================================================
extern "C" void kernel_launch(void* const* d_in, const int* in_sizes, int n_in,
                              void* d_out, int out_size) {
    (void)in_sizes; (void)n_in; (void)out_size;
    const float* a = (const float*)d_in[0];
    const float* b = (const float*)d_in[1];
    float* out = (float*)d_out;

    int nsm = 0;
    cudaDeviceGetAttribute(&nsm, cudaDevAttrMultiProcessorCount, 0);
    if (nsm <= 0) nsm = 148;

    cudaFuncSetAttribute(gemm_lse_kernel,
                         cudaFuncAttributeMaxDynamicSharedMemorySize, SMEM_TOTAL);

    quantize_a_pos_kernel<<<BA, 128>>>(a, b);
    quantize_b_kernel<<<BB, 128>>>(b);
    reset_ctr_kernel<<<1, 1>>>((unsigned int)nsm);
    gemm_lse_kernel<<<nsm, THREADS, SMEM_TOTAL>>>();
    combine_kernel<<<ROWBLOCKS, 128>>>();
    final_kernel<<<1, 64>>>(out);
}

// round 14
// speedup vs baseline: 2.7769x; 1.0480x over previous
#include <cuda_runtime.h>
#include <cuda_bf16.h>
#include <stdint.h>

// ============================================================================
// Problem constants
// ============================================================================
#define BA 8192
#define BB 16384
#define DIM 1024
#define LOSS_SCALE 20.0f
#define LOG2E 1.4426950408889634f
#define M_FIX 21.0f                    // global logit bound (|logit| <= ~20.2)
#define M2 (M_FIX * LOG2E)             // fixed max in log2 domain

#define TM 128            // item rows
#define TN 256            // item cols
#define TKS 128           // K bytes per pipeline stage
#define STAGES 2
#define KSTAGES (DIM / TKS)           // 8 stages per item
#define NCHUNK (BB / TN)              // 64 column chunks
#define ROWBLOCKS (BA / TM)           // 64
#define NITEMS (ROWBLOCKS * NCHUNK)   // 4096 work items
#define THREADS 256

// ============================================================================
// Device scratch
// ============================================================================
__device__ __align__(128) int8_t g_a_q[(size_t)BA * DIM];   // 8 MB
__device__ __align__(128) int8_t g_b_q[(size_t)BB * DIM];   // 16 MB
__device__ float g_saL[BA];    // 20 * log2e * per-row dequant scale for A
__device__ float g_sb[BB];     // per-row dequant scale for B
__device__ float g_pos[BA];
__device__ float g_ps[NCHUNK * BA];   // transposed: [chunk][row] partial sums
__device__ float g_part[ROWBLOCKS];
__device__ unsigned int g_ctr;

// ============================================================================
// SMEM layout. int8 rows: 128 data bytes + 16 pad = 144 B pitch.
// ============================================================================
#define PITCH_B 144
#define A_STAGE_BYTES (128 * PITCH_B)        // 18432
#define B_STAGE_BYTES (256 * PITCH_B)        // 36864
#define SM_A(stg) ((stg) * A_STAGE_BYTES)
#define SM_B(stg) (STAGES * A_STAGE_BYTES + (stg) * B_STAGE_BYTES)
#define SM_RED (STAGES * (A_STAGE_BYTES + B_STAGE_BYTES))  // float red[4][128]
#define SMEM_TOTAL (SM_RED + 4 * 128 * 4 + 32)             // ~112.6 KB

// ============================================================================
// PTX helpers
// ============================================================================
__device__ __forceinline__ uint32_t smem_to_u32(const void* p) {
    uint32_t a;
    asm("{ .reg .u64 t; cvta.to.shared.u64 t, %1; cvt.u32.u64 %0, t; }"
        : "=r"(a) : "l"(p));
    return a;
}

__device__ __forceinline__ void cp_async16(uint32_t s, const void* g) {
    asm volatile("cp.async.cg.shared.global [%0], [%1], 16;"
                 :: "r"(s), "l"(g) : "memory");
}
#define CP_COMMIT() asm volatile("cp.async.commit_group;" ::: "memory")
#define CP_WAIT(n)  asm volatile("cp.async.wait_group %0;" :: "n"(n) : "memory")

__device__ __forceinline__ void ldm_x4(uint32_t& r0, uint32_t& r1, uint32_t& r2,
                                       uint32_t& r3, uint32_t addr) {
    asm volatile("ldmatrix.sync.aligned.m8n8.x4.shared.b16 {%0,%1,%2,%3}, [%4];"
                 : "=r"(r0), "=r"(r1), "=r"(r2), "=r"(r3) : "r"(addr));
}

__device__ __forceinline__ void imma16832(int* c, uint32_t a0, uint32_t a1,
                                          uint32_t a2, uint32_t a3,
                                          uint32_t b0, uint32_t b1) {
    asm volatile(
        "mma.sync.aligned.m16n8k32.row.col.s32.s8.s8.s32 "
        "{%0,%1,%2,%3}, {%4,%5,%6,%7}, {%8,%9}, {%0,%1,%2,%3};"
        : "+r"(c[0]), "+r"(c[1]), "+r"(c[2]), "+r"(c[3])
        : "r"(a0), "r"(a1), "r"(a2), "r"(a3), "r"(b0), "r"(b1));
}

__global__ void reset_ctr_kernel(unsigned int v) { g_ctr = v; }

// ============================================================================
// Kernel 1a: quantize A + compute pos (reads both a and b rows once)
// ============================================================================
__global__ void __launch_bounds__(128) quantize_a_pos_kernel(const float* __restrict__ a,
                                                             const float* __restrict__ b) {
    int row = blockIdx.x;
    int t = threadIdx.x;
    const float4* a4 = (const float4*)a + (size_t)row * (DIM / 4);
    const float4* b4 = (const float4*)b + (size_t)row * (DIM / 4);
    float4 v0 = a4[t], v1 = a4[t + 128];
    float4 y0 = b4[t], y1 = b4[t + 128];
    float ss = v0.x * v0.x + v0.y * v0.y + v0.z * v0.z + v0.w * v0.w
             + v1.x * v1.x + v1.y * v1.y + v1.z * v1.z + v1.w * v1.w;
    float ma = fmaxf(fmaxf(fmaxf(fabsf(v0.x), fabsf(v0.y)), fmaxf(fabsf(v0.z), fabsf(v0.w))),
                     fmaxf(fmaxf(fabsf(v1.x), fabsf(v1.y)), fmaxf(fabsf(v1.z), fabsf(v1.w))));
    float dt = v0.x * y0.x + v0.y * y0.y + v0.z * y0.z + v0.w * y0.w
             + v1.x * y1.x + v1.y * y1.y + v1.z * y1.z + v1.w * y1.w;
    float nb = y0.x * y0.x + y0.y * y0.y + y0.z * y0.z + y0.w * y0.w
             + y1.x * y1.x + y1.y * y1.y + y1.z * y1.z + y1.w * y1.w;
    #pragma unroll
    for (int o = 16; o; o >>= 1) {
        ss += __shfl_xor_sync(0xffffffffu, ss, o);
        ma = fmaxf(ma, __shfl_xor_sync(0xffffffffu, ma, o));
        dt += __shfl_xor_sync(0xffffffffu, dt, o);
        nb += __shfl_xor_sync(0xffffffffu, nb, o);
    }
    __shared__ float wss[4], wma[4], wdt[4], wnb[4];
    if ((t & 31) == 0) { wss[t >> 5] = ss; wma[t >> 5] = ma; wdt[t >> 5] = dt; wnb[t >> 5] = nb; }
    __syncthreads();
    float inv = rsqrtf(wss[0] + wss[1] + wss[2] + wss[3]);
    float maxraw = fmaxf(fmaxf(wma[0], wma[1]), fmaxf(wma[2], wma[3]));
    float qs = 127.0f / maxraw;
    if (t == 0) {
        g_saL[row] = LOSS_SCALE * LOG2E * maxraw * inv * (1.0f / 127.0f);
        float dot = wdt[0] + wdt[1] + wdt[2] + wdt[3];
        float ib = rsqrtf(wnb[0] + wnb[1] + wnb[2] + wnb[3]);
        g_pos[row] = LOSS_SCALE * dot * inv * ib;
    }
    uint32_t p0 = ((uint32_t)(uint8_t)(int8_t)__float2int_rn(v0.x * qs))
                | ((uint32_t)(uint8_t)(int8_t)__float2int_rn(v0.y * qs) << 8)
                | ((uint32_t)(uint8_t)(int8_t)__float2int_rn(v0.z * qs) << 16)
                | ((uint32_t)(uint8_t)(int8_t)__float2int_rn(v0.w * qs) << 24);
    uint32_t p1 = ((uint32_t)(uint8_t)(int8_t)__float2int_rn(v1.x * qs))
                | ((uint32_t)(uint8_t)(int8_t)__float2int_rn(v1.y * qs) << 8)
                | ((uint32_t)(uint8_t)(int8_t)__float2int_rn(v1.z * qs) << 16)
                | ((uint32_t)(uint8_t)(int8_t)__float2int_rn(v1.w * qs) << 24);
    uint32_t* drow = (uint32_t*)(g_a_q + (size_t)row * DIM);
    drow[t] = p0;
    drow[128 + t] = p1;
}

// ============================================================================
// Kernel 1b: quantize B
// ============================================================================
__global__ void __launch_bounds__(128) quantize_b_kernel(const float* __restrict__ src) {
    int row = blockIdx.x;
    int t = threadIdx.x;
    const float4* s4 = (const float4*)src + (size_t)row * (DIM / 4);
    float4 v0 = s4[t];
    float4 v1 = s4[t + 128];
    float ss = v0.x * v0.x + v0.y * v0.y + v0.z * v0.z + v0.w * v0.w
             + v1.x * v1.x + v1.y * v1.y + v1.z * v1.z + v1.w * v1.w;
    float ma = fmaxf(fmaxf(fmaxf(fabsf(v0.x), fabsf(v0.y)), fmaxf(fabsf(v0.z), fabsf(v0.w))),
                     fmaxf(fmaxf(fabsf(v1.x), fabsf(v1.y)), fmaxf(fabsf(v1.z), fabsf(v1.w))));
    #pragma unroll
    for (int o = 16; o; o >>= 1) {
        ss += __shfl_xor_sync(0xffffffffu, ss, o);
        ma = fmaxf(ma, __shfl_xor_sync(0xffffffffu, ma, o));
    }
    __shared__ float wss[4], wma[4];
    if ((t & 31) == 0) { wss[t >> 5] = ss; wma[t >> 5] = ma; }
    __syncthreads();
    float inv = rsqrtf(wss[0] + wss[1] + wss[2] + wss[3]);
    float maxraw = fmaxf(fmaxf(wma[0], wma[1]), fmaxf(wma[2], wma[3]));
    float qs = 127.0f / maxraw;
    if (t == 0) g_sb[row] = maxraw * inv * (1.0f / 127.0f);
    uint32_t p0 = ((uint32_t)(uint8_t)(int8_t)__float2int_rn(v0.x * qs))
                | ((uint32_t)(uint8_t)(int8_t)__float2int_rn(v0.y * qs) << 8)
                | ((uint32_t)(uint8_t)(int8_t)__float2int_rn(v0.z * qs) << 16)
                | ((uint32_t)(uint8_t)(int8_t)__float2int_rn(v0.w * qs) << 24);
    uint32_t p1 = ((uint32_t)(uint8_t)(int8_t)__float2int_rn(v1.x * qs))
                | ((uint32_t)(uint8_t)(int8_t)__float2int_rn(v1.y * qs) << 8)
                | ((uint32_t)(uint8_t)(int8_t)__float2int_rn(v1.z * qs) << 16)
                | ((uint32_t)(uint8_t)(int8_t)__float2int_rn(v1.w * qs) << 24);
    uint32_t* drow = (uint32_t*)(g_b_q + (size_t)row * DIM);
    drow[t] = p0;
    drow[128 + t] = p1;
}

// ============================================================================
// Kernel 2: persistent fused int8 GEMM (IMMA k32) + fixed-max exp-sum partials
//   Item = (rb, chunk): 128x256 tile over full K. Work stolen via g_ctr.
//   Epilogue: s = sum exp2(logit*log2e - M2); no max tracking (logits bounded).
// ============================================================================
__global__ void __launch_bounds__(THREADS, 1) gemm_lse_kernel() {
    extern __shared__ char sm[];
    uint32_t sb = smem_to_u32(sm);

    int t = threadIdx.x;
    int lane = t & 31;
    int w = t >> 5;
    int wm = w >> 2;             // 0..1
    int wn = w & 3;              // 0..3

    float* red = (float*)(sm + SM_RED);          // [4][128]
    __shared__ int sm_next;

    int acc[4][8][4];
    #pragma unroll
    for (int mt = 0; mt < 4; mt++)
        #pragma unroll
        for (int nt = 0; nt < 8; nt++)
            #pragma unroll
            for (int j = 0; j < 4; j++) acc[mt][nt][j] = 0;

    // --- issue one stage of cp.asyncs for item `it`, k-chunk `kc`, buffer `buf`
    auto issue = [&](int it, int kc, int buf) {
        if (it < NITEMS) {
            int rb_ = it >> 6;
            int ch_ = it & 63;
            const char* ag = (const char*)g_a_q + (size_t)(rb_ * TM) * DIM;
            const char* bg = (const char*)g_b_q + (size_t)(ch_ * TN) * DIM;
            uint32_t sa = sb + SM_A(buf);
            uint32_t sbB = sb + SM_B(buf);
            size_t koff = (size_t)kc * TKS;
            #pragma unroll
            for (int i = 0; i < 4; i++) {
                int c = t + i * THREADS;
                int row = c >> 3, seg = c & 7;
                cp_async16(sa + row * PITCH_B + seg * 16,
                           ag + (size_t)row * DIM + koff + seg * 16);
            }
            #pragma unroll
            for (int i = 0; i < 8; i++) {
                int c = t + i * THREADS;
                int row = c >> 3, seg = c & 7;
                cp_async16(sbB + row * PITCH_B + seg * 16,
                           bg + (size_t)row * DIM + koff + seg * 16);
            }
        }
        CP_COMMIT();
    };

    int item = blockIdx.x;
    int ibuf = 0, cbuf = 0;
    issue(item, 0, ibuf); ibuf ^= 1;

    while (item < NITEMS) {
        int rb = item >> 6;
        int chunk = item & 63;

        // per-thread A row dequant scales (include 20*log2e)
        float sav[4][2];
        #pragma unroll
        for (int mt = 0; mt < 4; mt++)
            #pragma unroll
            for (int h = 0; h < 2; h++)
                sav[mt][h] = g_saL[rb * TM + wm * 64 + mt * 16 + h * 8 + (lane >> 2)];

        for (int s = 0; s < KSTAGES; s++) {
            CP_WAIT(0);
            __syncthreads();
            if (s == 0 && t == 0) sm_next = (int)atomicAdd(&g_ctr, 1u);
            if (s < KSTAGES - 1) issue(item, s + 1, ibuf);
            else issue(sm_next, 0, ibuf);   // sm_next visible: written s0, synced s1
            ibuf ^= 1;

            // A frags: 16 rows per mt; lanes 0-15: rows, lanes 16-31: +16B k-half
            uint32_t saA = sb + SM_A(cbuf)
                         + (uint32_t)(wm * 64 + (lane & 15)) * PITCH_B
                         + ((lane >> 4) * 16);
            // B frags: nt-pair per ldm_x4 (16 n-rows)
            uint32_t sbF = sb + SM_B(cbuf)
                         + (uint32_t)(wn * 64 + ((lane >> 4) & 1) * 8 + (lane & 7)) * PITCH_B
                         + (((lane >> 3) & 1) * 16);
            cbuf ^= 1;

            #pragma unroll
            for (int kk = 0; kk < 4; kk++) {            // 4 x k32 per 128B stage
                uint32_t a0[4], a1[4], a2[4], a3[4];
                uint32_t b0[8], b1[8];
                #pragma unroll
                for (int mt = 0; mt < 4; mt++)
                    ldm_x4(a0[mt], a1[mt], a2[mt], a3[mt],
                           saA + mt * 16 * PITCH_B + kk * 32);
                #pragma unroll
                for (int p = 0; p < 4; p++)
                    ldm_x4(b0[2 * p], b1[2 * p], b0[2 * p + 1], b1[2 * p + 1],
                           sbF + p * 16 * PITCH_B + kk * 32);
                #pragma unroll
                for (int mt = 0; mt < 4; mt++)
                    #pragma unroll
                    for (int nt = 0; nt < 8; nt++)
                        imma16832(acc[mt][nt], a0[mt], a1[mt], a2[mt], a3[mt],
                                  b0[nt], b1[nt]);
            }

            if (s == KSTAGES - 1) {
                // ---- fixed-max exp-sum epilogue for this item's 256 cols ----
                const float* sbp = g_sb + chunk * TN + wn * 64 + (lane & 3) * 2;
                float sbv[8][2];
                #pragma unroll
                for (int nt = 0; nt < 8; nt++) {
                    sbv[nt][0] = sbp[nt * 8];
                    sbv[nt][1] = sbp[nt * 8 + 1];
                }
                #pragma unroll
                for (int mt = 0; mt < 4; mt++) {
                    #pragma unroll
                    for (int h = 0; h < 2; h++) {
                        float rs = sav[mt][h];
                        float ssum = 0.f;
                        #pragma unroll
                        for (int nt = 0; nt < 8; nt++) {
                            #pragma unroll
                            for (int j = 0; j < 2; j++) {
                                float f = (float)acc[mt][nt][2 * h + j] * rs;
                                ssum += exp2f(fmaf(f, sbv[nt][j], -M2));
                                acc[mt][nt][2 * h + j] = 0;
                            }
                        }
                        // quad reduce (lanes xor 1,2 share the same output row)
                        ssum += __shfl_xor_sync(0xffffffffu, ssum, 1);
                        ssum += __shfl_xor_sync(0xffffffffu, ssum, 2);
                        if ((lane & 3) == 0) {
                            int row = wm * 64 + mt * 16 + h * 8 + (lane >> 2);
                            red[wn * 128 + row] = ssum;
                        }
                    }
                }
                __syncthreads();
                if (t < 128) {
                    float S = (red[t] + red[128 + t]) + (red[256 + t] + red[384 + t]);
                    g_ps[chunk * BA + rb * TM + t] = S;
                }
                // red[] not touched again until next item's epilogue (8 stages away)
            }
        }
        item = sm_next;
    }
    CP_WAIT(0);   // drain dangling empty commits
}

// ============================================================================
// Kernel 3/4: deterministic combine + mean.  lse_row = ln(S_total) + M_FIX
// ============================================================================
__global__ void __launch_bounds__(128) combine_kernel() {
    int row = blockIdx.x * 128 + threadIdx.x;
    float S = 0.f;
    #pragma unroll 8
    for (int c = 0; c < NCHUNK; c++)
        S += g_ps[c * BA + row];
    float li = logf(S) + M_FIX - g_pos[row];
    #pragma unroll
    for (int o = 16; o; o >>= 1) li += __shfl_xor_sync(0xffffffffu, li, o);
    __shared__ float ws[4];
    if ((threadIdx.x & 31) == 0) ws[threadIdx.x >> 5] = li;
    __syncthreads();
    if (threadIdx.x == 0) g_part[blockIdx.x] = ws[0] + ws[1] + ws[2] + ws[3];
}

__global__ void __launch_bounds__(64) final_kernel(float* __restrict__ out) {
    float v = g_part[threadIdx.x];
    #pragma unroll
    for (int o = 16; o; o >>= 1) v += __shfl_xor_sync(0xffffffffu, v, o);
    __shared__ float ws[2];
    if ((threadIdx.x & 31) == 0) ws[threadIdx.x >> 5] = v;
    __syncthreads();
    if (threadIdx.x == 0) out[0] = (ws[0] + ws[1]) * (1.0f / (float)BA);
}

// ============================================================================
// Launch
// ============================================================================
extern "C" void kernel_launch(void* const* d_in, const int* in_sizes, int n_in,
                              void* d_out, int out_size) {
    (void)in_sizes; (void)n_in; (void)out_size;
    const float* a = (const float*)d_in[0];
    const float* b = (const float*)d_in[1];
    float* out = (float*)d_out;

    int nsm = 0;
    cudaDeviceGetAttribute(&nsm, cudaDevAttrMultiProcessorCount, 0);
    if (nsm <= 0) nsm = 148;

    cudaFuncSetAttribute(gemm_lse_kernel,
                         cudaFuncAttributeMaxDynamicSharedMemorySize, SMEM_TOTAL);

    quantize_a_pos_kernel<<<BA, 128>>>(a, b);
    quantize_b_kernel<<<BB, 128>>>(b);
    reset_ctr_kernel<<<1, 1>>>((unsigned int)nsm);
    gemm_lse_kernel<<<nsm, THREADS, SMEM_TOTAL>>>();
    combine_kernel<<<ROWBLOCKS, 128>>>();
    final_kernel<<<1, 64>>>(out);
}